// round 1
// baseline (speedup 1.0000x reference)
#include <cuda_runtime.h>
#include <math.h>
#include <math_constants.h>

#define NPTS 8192
#define DIM  128
#define KNB  8
#define BT   128   // GEMM tile (BT x BT)
#define KC   32    // K chunk

// Scratch (allocation-free rule: __device__ globals)
__device__ float g_dot[(size_t)NPTS * NPTS];   // raw dot products x_i . x_j
__device__ float g_sq[NPTS];                   // ||x_i||^2
__device__ float g_loss[NPTS];                 // per-row loss

// ---------------------------------------------------------------------------
// Kernel 0: squared norms, one warp per row
// ---------------------------------------------------------------------------
__global__ void sqnorm_kernel(const float* __restrict__ x, int n) {
    int warp = (blockIdx.x * blockDim.x + threadIdx.x) >> 5;
    int lane = threadIdx.x & 31;
    if (warp >= n) return;
    float4 v = ((const float4*)(x + (size_t)warp * DIM))[lane];
    float s = v.x * v.x + v.y * v.y + v.z * v.z + v.w * v.w;
    #pragma unroll
    for (int o = 16; o; o >>= 1) s += __shfl_xor_sync(0xffffffffu, s, o);
    if (lane == 0) g_sq[warp] = s;
}

// ---------------------------------------------------------------------------
// Kernel 1: symmetric tiled SGEMM of x @ x^T into g_dot.
// One CTA per upper-triangular 128x128 block pair; writes tile + transpose.
// ---------------------------------------------------------------------------
__global__ __launch_bounds__(256) void gemm_kernel(const float* __restrict__ x, int n) {
    const int nb = n / BT;
    // decode linear block index -> (bi, bj), bi <= bj
    int rem = blockIdx.x;
    int bi = 0;
    while (rem >= nb - bi) { rem -= nb - bi; bi++; }
    int bj = bi + rem;

    __shared__ float As[KC][BT + 4];
    __shared__ float Bs[KC][BT + 4];

    const int tid = threadIdx.x;
    const int tx = tid & 15;      // 16 thread cols
    const int ty = tid >> 4;      // 16 thread rows

    float c[8][8];
    #pragma unroll
    for (int m = 0; m < 8; m++)
        #pragma unroll
        for (int q = 0; q < 8; q++) c[m][q] = 0.0f;

    const float* Ag = x + (size_t)bi * BT * DIM;
    const float* Bg = x + (size_t)bj * BT * DIM;

    for (int k0 = 0; k0 < DIM; k0 += KC) {
        // Load 128 rows x 32 k (1024 float4), 4 float4 per thread, k-major smem
        #pragma unroll
        for (int r = 0; r < 4; r++) {
            int idx = tid + r * 256;      // 0..1023
            int row = idx >> 3;           // 8 float4 per row-chunk
            int q   = idx & 7;
            float4 a = *(const float4*)(Ag + (size_t)row * DIM + k0 + q * 4);
            As[q * 4 + 0][row] = a.x; As[q * 4 + 1][row] = a.y;
            As[q * 4 + 2][row] = a.z; As[q * 4 + 3][row] = a.w;
            float4 b = *(const float4*)(Bg + (size_t)row * DIM + k0 + q * 4);
            Bs[q * 4 + 0][row] = b.x; Bs[q * 4 + 1][row] = b.y;
            Bs[q * 4 + 2][row] = b.z; Bs[q * 4 + 3][row] = b.w;
        }
        __syncthreads();

        #pragma unroll
        for (int kk = 0; kk < KC; kk++) {
            float a[8], b[8];
            #pragma unroll
            for (int m = 0; m < 8; m++) a[m] = As[kk][ty * 8 + m];
            #pragma unroll
            for (int q = 0; q < 8; q++) b[q] = Bs[kk][tx * 8 + q];
            #pragma unroll
            for (int m = 0; m < 8; m++)
                #pragma unroll
                for (int q = 0; q < 8; q++) c[m][q] = fmaf(a[m], b[q], c[m][q]);
        }
        __syncthreads();
    }

    const size_t Ns = (size_t)n;
    const int i0 = bi * BT + ty * 8;
    const int j0 = bj * BT + tx * 8;
    #pragma unroll
    for (int m = 0; m < 8; m++) {
        #pragma unroll
        for (int q = 0; q < 8; q++) {
            float v = c[m][q];
            g_dot[(size_t)(i0 + m) * Ns + (j0 + q)] = v;
            g_dot[(size_t)(j0 + q) * Ns + (i0 + m)] = v;
        }
    }
}

// ---------------------------------------------------------------------------
// Kernel 2: per-row epilogue. One CTA per row.
//  d2 = sq_i + sq_j - 2*dot (clamped), denom = sum exp(-sqrt(d2)) over j!=i,
//  find 8 smallest d2, loss_i = mean(sqrt(top8)) + log(denom)
// ---------------------------------------------------------------------------
__global__ __launch_bounds__(256) void row_kernel(int n) {
    const int i = blockIdx.x;
    const int tid = threadIdx.x;
    const float* __restrict__ row = g_dot + (size_t)i * n;
    const float sqi = g_sq[i];

    float denom = 0.0f;
    float t8[KNB];
    #pragma unroll
    for (int q = 0; q < KNB; q++) t8[q] = CUDART_INF_F;
    float tmax = CUDART_INF_F;

    for (int j = tid; j < n; j += 256) {
        if (j == i) continue;
        float d2 = fmaxf(sqi + g_sq[j] - 2.0f * row[j], 0.0f);
        float d = sqrtf(d2);
        denom += __expf(-d);
        if (d2 < tmax) {
            // replace current max of t8 with d2
            int mi = 0; float mv = t8[0];
            #pragma unroll
            for (int q = 1; q < KNB; q++) if (t8[q] > mv) { mv = t8[q]; mi = q; }
            t8[mi] = d2;
            tmax = t8[0];
            #pragma unroll
            for (int q = 1; q < KNB; q++) tmax = fmaxf(tmax, t8[q]);
        }
    }

    __shared__ float cand[256 * KNB];
    __shared__ float sv[256];
    __shared__ int   si[256];
    __shared__ float s_denom;
    __shared__ int   s_win;

    #pragma unroll
    for (int q = 0; q < KNB; q++) cand[tid * KNB + q] = t8[q];

    // denom reduction
    sv[tid] = denom;
    __syncthreads();
    for (int o = 128; o; o >>= 1) {
        if (tid < o) sv[tid] += sv[tid + o];
        __syncthreads();
    }
    if (tid == 0) s_denom = sv[0];
    __syncthreads();

    // 8 rounds of global argmin over 2048 candidates
    float dsum = 0.0f;  // meaningful on tid 0 only
    for (int r = 0; r < KNB; r++) {
        float m = CUDART_INF_F; int mi = -1;
        for (int q = tid; q < 256 * KNB; q += 256)
            if (cand[q] < m) { m = cand[q]; mi = q; }
        sv[tid] = m; si[tid] = mi;
        __syncthreads();
        for (int o = 128; o; o >>= 1) {
            if (tid < o && sv[tid + o] < sv[tid]) { sv[tid] = sv[tid + o]; si[tid] = si[tid + o]; }
            __syncthreads();
        }
        if (tid == 0) {
            s_win = si[0];
            dsum += sqrtf(fmaxf(sv[0], 0.0f));
            cand[s_win] = CUDART_INF_F;
        }
        __syncthreads();
    }

    if (tid == 0)
        g_loss[i] = dsum * (1.0f / KNB) + logf(s_denom);
}

// ---------------------------------------------------------------------------
// Kernel 3: final reduction -> scalar
// ---------------------------------------------------------------------------
__global__ void final_kernel(float* __restrict__ out, int n) {
    __shared__ float sv[256];
    const int tid = threadIdx.x;
    float s = 0.0f;
    for (int i = tid; i < n; i += 256) s += g_loss[i];
    sv[tid] = s;
    __syncthreads();
    for (int o = 128; o; o >>= 1) {
        if (tid < o) sv[tid] += sv[tid + o];
        __syncthreads();
    }
    if (tid == 0) out[0] = sv[0] / (float)n;
}

// ---------------------------------------------------------------------------
extern "C" void kernel_launch(void* const* d_in, const int* in_sizes, int n_in,
                              void* d_out, int out_size) {
    const float* x = (const float*)d_in[0];
    float* out = (float*)d_out;
    const int n = in_sizes[0] / DIM;   // 8192
    const int nb = n / BT;             // 64
    const int tri_blocks = nb * (nb + 1) / 2;  // 2080

    sqnorm_kernel<<<(n + 7) / 8, 256>>>(x, n);
    gemm_kernel<<<tri_blocks, 256>>>(x, n);
    row_kernel<<<n, 256>>>(n);
    final_kernel<<<1, 256>>>(out, n);
}

// round 3
// speedup vs baseline: 1.7385x; 1.7385x over previous
#include <cuda_runtime.h>
#include <cuda_bf16.h>
#include <math.h>
#include <math_constants.h>
#include <cstdint>

#define NPTS 8192
#define DIM  128
#define KNB  8
#define KPACK 384          // bf16 [hi|lo|hi] x [hi|hi|lo]
#define TM   128
#define TN   256
#define KC   64            // k per chunk (128 bytes bf16)
#define NCHUNK 6

// ------------------------- device scratch (no allocs) -----------------------
__device__ float g_dot[(size_t)NPTS * NPTS];
__device__ float g_sq[NPTS];
__device__ float g_loss[NPTS];
__device__ uint4 g_pa[(size_t)NPTS * 48];   // 48 uint4 = 384 bf16 per row
__device__ uint4 g_pb[(size_t)NPTS * 48];

// ------------------------- helpers ------------------------------------------
__device__ __forceinline__ uint32_t smem_u32(const void* p) {
    uint32_t a;
    asm("{ .reg .u64 t; cvta.to.shared.u64 t, %1; cvt.u32.u64 %0, t; }"
        : "=r"(a) : "l"(p));
    return a;
}
#define SWZ(o) ((o) ^ (((o) >> 3) & 0x70))

#define CP_ASYNC16(dst, src) \
    asm volatile("cp.async.cg.shared.global [%0], [%1], 16;" \
                 :: "r"(dst), "l"(src) : "memory")
#define CP_COMMIT() asm volatile("cp.async.commit_group;" ::: "memory")
#define CP_WAIT(N)  asm volatile("cp.async.wait_group %0;" :: "n"(N) : "memory")

#define LDSM_X4(r0, r1, r2, r3, a) \
    asm volatile("ldmatrix.sync.aligned.m8n8.x4.shared.b16 {%0,%1,%2,%3}, [%4];" \
                 : "=r"(r0), "=r"(r1), "=r"(r2), "=r"(r3) : "r"(a))

#define MMA_BF16(c, a, b) \
    asm volatile("mma.sync.aligned.m16n8k16.row.col.f32.bf16.bf16.f32 " \
                 "{%0,%1,%2,%3}, {%4,%5,%6,%7}, {%8,%9}, {%0,%1,%2,%3};" \
                 : "+f"((c)[0]), "+f"((c)[1]), "+f"((c)[2]), "+f"((c)[3]) \
                 : "r"((a)[0]), "r"((a)[1]), "r"((a)[2]), "r"((a)[3]), \
                   "r"((b)[0]), "r"((b)[1]))

// SMEM: 2 stages x (A 16KB + B 32KB) = 96KB
#define STAGE_SZ 49152
#define OFF_B    16384
#define SMEM_TOTAL (2 * STAGE_SZ)

// ---------------------------------------------------------------------------
// pack x into bf16 hi/lo arrays
// ---------------------------------------------------------------------------
__global__ void pack_kernel(const float* __restrict__ x) {
    int t = blockIdx.x * blockDim.x + threadIdx.x;
    int i = t >> 7, col = t & 127;
    float v = x[(size_t)i * DIM + col];
    __nv_bfloat16 hi = __float2bfloat16(v);
    __nv_bfloat16 lo = __float2bfloat16(v - __bfloat162float(hi));
    __nv_bfloat16* pa = (__nv_bfloat16*)g_pa;
    __nv_bfloat16* pb = (__nv_bfloat16*)g_pb;
    size_t base = (size_t)i * KPACK;
    pa[base + col] = hi; pa[base + 128 + col] = lo; pa[base + 256 + col] = hi;
    pb[base + col] = hi; pb[base + 128 + col] = hi; pb[base + 256 + col] = lo;
}

// ---------------------------------------------------------------------------
// squared norms (one warp per row)
// ---------------------------------------------------------------------------
__global__ void sqnorm_kernel(const float* __restrict__ x, int n) {
    int warp = (blockIdx.x * blockDim.x + threadIdx.x) >> 5;
    int lane = threadIdx.x & 31;
    if (warp >= n) return;
    float4 v = ((const float4*)(x + (size_t)warp * DIM))[lane];
    float s = v.x * v.x + v.y * v.y + v.z * v.z + v.w * v.w;
    #pragma unroll
    for (int o = 16; o; o >>= 1) s += __shfl_xor_sync(0xffffffffu, s, o);
    if (lane == 0) g_sq[warp] = s;
}

// ---------------------------------------------------------------------------
// HMMA bf16 GEMM: CTA 128x256, 8 warps of 64x64, K=384, cp.async pipelined
// ---------------------------------------------------------------------------
__device__ __forceinline__ void load_chunk(uint32_t sb, int stage, int c,
                                           int i0, int j0, int tid) {
    uint32_t s = sb + stage * STAGE_SZ;
    #pragma unroll
    for (int r = 0; r < 4; r++) {                 // A: 1024 uint4
        int idx = tid + r * 256;
        int row = idx >> 3, q = idx & 7;
        const uint4* src = &g_pa[(size_t)(i0 + row) * 48 + c * 8 + q];
        CP_ASYNC16(s + SWZ(row * 128 + q * 16), src);
    }
    #pragma unroll
    for (int r = 0; r < 8; r++) {                 // B: 2048 uint4
        int idx = tid + r * 256;
        int row = idx >> 3, q = idx & 7;
        const uint4* src = &g_pb[(size_t)(j0 + row) * 48 + c * 8 + q];
        CP_ASYNC16(s + OFF_B + SWZ(row * 128 + q * 16), src);
    }
    CP_COMMIT();
}

__global__ __launch_bounds__(256, 1) void hmma_gemm(int n) {
    extern __shared__ __align__(16) char smem[];
    const uint32_t sb = smem_u32(smem);
    const int tid = threadIdx.x;
    const int wid = tid >> 5;
    const int lane = tid & 31;
    const int wm = wid & 1;          // 2 m-warps
    const int wn = wid >> 1;         // 4 n-warps
    const int mr = wm * 64;
    const int nr = wn * 64;

    const int i0 = blockIdx.y * TM;
    const int j0 = blockIdx.x * TN;

    // ldmatrix lane addressing: rows l&15, col half (l>>4)*8
    const int row_off = lane & 15;
    const int colh2 = (lane >> 4) * 16;              // bytes
    const uint32_t aRow = (uint32_t)(mr + row_off) * 128;
    const uint32_t bRow = (uint32_t)(nr + row_off) * 128;

    float acc[4][8][4];
    #pragma unroll
    for (int i = 0; i < 4; i++)
        #pragma unroll
        for (int j = 0; j < 8; j++)
            #pragma unroll
            for (int q = 0; q < 4; q++) acc[i][j][q] = 0.0f;

    load_chunk(sb, 0, 0, i0, j0, tid);

    for (int c = 0; c < NCHUNK; c++) {
        if (c + 1 < NCHUNK) {
            load_chunk(sb, (c + 1) & 1, c + 1, i0, j0, tid);
            CP_WAIT(1);
        } else {
            CP_WAIT(0);
        }
        __syncthreads();

        uint32_t sA = sb + (c & 1) * STAGE_SZ;
        uint32_t sB = sA + OFF_B;

        #pragma unroll
        for (int ks = 0; ks < 4; ks++) {
            uint32_t colb = ks * 32 + colh2;
            uint32_t aF[4][4], bF[8][2];
            #pragma unroll
            for (int i = 0; i < 4; i++) {
                uint32_t ad = sA + SWZ(aRow + i * 2048 + colb);
                LDSM_X4(aF[i][0], aF[i][1], aF[i][2], aF[i][3], ad);
            }
            #pragma unroll
            for (int jj = 0; jj < 4; jj++) {
                uint32_t r0, r1, r2, r3;
                uint32_t bd = sB + SWZ(bRow + jj * 2048 + colb);
                LDSM_X4(r0, r1, r2, r3, bd);
                bF[2 * jj][0] = r0; bF[2 * jj][1] = r2;
                bF[2 * jj + 1][0] = r1; bF[2 * jj + 1][1] = r3;
            }
            #pragma unroll
            for (int i = 0; i < 4; i++)
                #pragma unroll
                for (int j = 0; j < 8; j++)
                    MMA_BF16(acc[i][j], aF[i], bF[j]);
        }
        __syncthreads();
    }

    // Epilogue: direct v2 stores (32B sectors filled across lanes)
    const int g = lane >> 2, t = lane & 3;
    #pragma unroll
    for (int i = 0; i < 4; i++) {
        int r0 = i0 + mr + i * 16 + g;
        #pragma unroll
        for (int j = 0; j < 8; j++) {
            int cc = j0 + nr + j * 8 + t * 2;
            float2 v0 = make_float2(acc[i][j][0], acc[i][j][1]);
            float2 v1 = make_float2(acc[i][j][2], acc[i][j][3]);
            *(float2*)(g_dot + (size_t)r0 * n + cc) = v0;
            *(float2*)(g_dot + (size_t)(r0 + 8) * n + cc) = v1;
        }
    }
}

// ---------------------------------------------------------------------------
// per-row epilogue: denom + top-8 + loss
// ---------------------------------------------------------------------------
__global__ __launch_bounds__(256) void row_kernel(int n) {
    const int i = blockIdx.x;
    const int tid = threadIdx.x;
    const float4* __restrict__ row4 = (const float4*)(g_dot + (size_t)i * n);
    const float4* __restrict__ sq4 = (const float4*)g_sq;
    const float sqi = g_sq[i];

    float denom = 0.0f;
    float t8[KNB];
    #pragma unroll
    for (int q = 0; q < KNB; q++) t8[q] = CUDART_INF_F;
    float tmax = CUDART_INF_F;

    for (int it = 0; it < NPTS / 1024; it++) {
        int j4 = it * 256 + tid;
        float4 dv = row4[j4];
        float4 qv = sq4[j4];
        int jb = j4 * 4;
        #pragma unroll
        for (int e = 0; e < 4; e++) {
            float dot = e == 0 ? dv.x : e == 1 ? dv.y : e == 2 ? dv.z : dv.w;
            float sqj = e == 0 ? qv.x : e == 1 ? qv.y : e == 2 ? qv.z : qv.w;
            int j = jb + e;
            float d2 = fmaxf(sqi + sqj - 2.0f * dot, 0.0f);
            float d = (d2 > 0.0f) ? d2 * rsqrtf(d2) : 0.0f;
            float ex = __expf(-d);
            bool self = (j == i);
            denom += self ? 0.0f : ex;
            float cd2 = self ? CUDART_INF_F : d2;
            if (cd2 < tmax) {
                int mi = 0; float mv = t8[0];
                #pragma unroll
                for (int q = 1; q < KNB; q++) if (t8[q] > mv) { mv = t8[q]; mi = q; }
                t8[mi] = cd2;
                tmax = t8[0];
                #pragma unroll
                for (int q = 1; q < KNB; q++) tmax = fmaxf(tmax, t8[q]);
            }
        }
    }

    __shared__ float cand[256 * KNB];
    __shared__ float sv[256];
    __shared__ int   si[256];
    __shared__ float s_denom;

    #pragma unroll
    for (int q = 0; q < KNB; q++) cand[tid * KNB + q] = t8[q];

    sv[tid] = denom;
    __syncthreads();
    for (int o = 128; o; o >>= 1) {
        if (tid < o) sv[tid] += sv[tid + o];
        __syncthreads();
    }
    if (tid == 0) s_denom = sv[0];
    __syncthreads();

    float dsum = 0.0f;   // valid on tid 0
    for (int r = 0; r < KNB; r++) {
        float m = CUDART_INF_F; int mi = -1;
        for (int q = tid; q < 256 * KNB; q += 256)
            if (cand[q] < m) { m = cand[q]; mi = q; }
        sv[tid] = m; si[tid] = mi;
        __syncthreads();
        for (int o = 128; o; o >>= 1) {
            if (tid < o && sv[tid + o] < sv[tid]) { sv[tid] = sv[tid + o]; si[tid] = si[tid + o]; }
            __syncthreads();
        }
        if (tid == 0) {
            float v = fmaxf(sv[0], 0.0f);
            dsum += (v > 0.0f) ? v * rsqrtf(v) : 0.0f;
            cand[si[0]] = CUDART_INF_F;
        }
        __syncthreads();
    }

    if (tid == 0)
        g_loss[i] = dsum * (1.0f / KNB) + __logf(s_denom);
}

// ---------------------------------------------------------------------------
__global__ void final_kernel(float* __restrict__ out, int n) {
    __shared__ float sv[256];
    const int tid = threadIdx.x;
    float s = 0.0f;
    for (int i = tid; i < n; i += 256) s += g_loss[i];
    sv[tid] = s;
    __syncthreads();
    for (int o = 128; o; o >>= 1) {
        if (tid < o) sv[tid] += sv[tid + o];
        __syncthreads();
    }
    if (tid == 0) out[0] = sv[0] / (float)n;
}

// ---------------------------------------------------------------------------
extern "C" void kernel_launch(void* const* d_in, const int* in_sizes, int n_in,
                              void* d_out, int out_size) {
    const float* x = (const float*)d_in[0];
    float* out = (float*)d_out;
    const int n = in_sizes[0] / DIM;   // 8192

    cudaFuncSetAttribute(hmma_gemm, cudaFuncAttributeMaxDynamicSharedMemorySize,
                         SMEM_TOTAL);

    pack_kernel<<<(n * DIM) / 256, 256>>>(x);
    sqnorm_kernel<<<(n + 7) / 8, 256>>>(x, n);
    hmma_gemm<<<dim3(n / TN, n / TM), 256, SMEM_TOTAL>>>(n);
    row_kernel<<<n, 256>>>(n);
    final_kernel<<<1, 256>>>(out, n);
}

// round 4
// speedup vs baseline: 2.0629x; 1.1866x over previous
#include <cuda_runtime.h>
#include <cuda_bf16.h>
#include <math.h>
#include <math_constants.h>
#include <cstdint>

#define NPTS 8192
#define DIM  128
#define KNB  8
#define KPACK 384          // bf16 [hi|lo|hi] x [hi|hi|lo]
#define TM   128
#define TN   256
#define NCHUNK 6

// ------------------------- device scratch (no allocs) -----------------------
__device__ float g_dot[(size_t)NPTS * NPTS];
__device__ float g_sq[NPTS];
__device__ float g_loss[NPTS];
__device__ uint4 g_pa[(size_t)NPTS * 48];
__device__ uint4 g_pb[(size_t)NPTS * 48];

// ------------------------- helpers ------------------------------------------
__device__ __forceinline__ uint32_t smem_u32(const void* p) {
    uint32_t a;
    asm("{ .reg .u64 t; cvta.to.shared.u64 t, %1; cvt.u32.u64 %0, t; }"
        : "=r"(a) : "l"(p));
    return a;
}
#define SWZ(o) ((o) ^ (((o) >> 3) & 0x70))

#define CP_ASYNC16(dst, src) \
    asm volatile("cp.async.cg.shared.global [%0], [%1], 16;" \
                 :: "r"(dst), "l"(src) : "memory")
#define CP_COMMIT() asm volatile("cp.async.commit_group;" ::: "memory")
#define CP_WAIT(N)  asm volatile("cp.async.wait_group %0;" :: "n"(N) : "memory")

#define LDSM_X4(r0, r1, r2, r3, a) \
    asm volatile("ldmatrix.sync.aligned.m8n8.x4.shared.b16 {%0,%1,%2,%3}, [%4];" \
                 : "=r"(r0), "=r"(r1), "=r"(r2), "=r"(r3) : "r"(a))

#define MMA_BF16(c, a, b) \
    asm volatile("mma.sync.aligned.m16n8k16.row.col.f32.bf16.bf16.f32 " \
                 "{%0,%1,%2,%3}, {%4,%5,%6,%7}, {%8,%9}, {%0,%1,%2,%3};" \
                 : "+f"((c)[0]), "+f"((c)[1]), "+f"((c)[2]), "+f"((c)[3]) \
                 : "r"((a)[0]), "r"((a)[1]), "r"((a)[2]), "r"((a)[3]), \
                   "r"((b)[0]), "r"((b)[1]))

// SMEM: 3 stages x (A 16KB + B 32KB) = 144KB
#define STAGE_SZ 49152
#define OFF_B    16384
#define SMEM_TOTAL (3 * STAGE_SZ)

// ---------------------------------------------------------------------------
__global__ void pack_kernel(const float* __restrict__ x) {
    int t = blockIdx.x * blockDim.x + threadIdx.x;
    int i = t >> 7, col = t & 127;
    float v = x[(size_t)i * DIM + col];
    __nv_bfloat16 hi = __float2bfloat16(v);
    __nv_bfloat16 lo = __float2bfloat16(v - __bfloat162float(hi));
    __nv_bfloat16* pa = (__nv_bfloat16*)g_pa;
    __nv_bfloat16* pb = (__nv_bfloat16*)g_pb;
    size_t base = (size_t)i * KPACK;
    pa[base + col] = hi; pa[base + 128 + col] = lo; pa[base + 256 + col] = hi;
    pb[base + col] = hi; pb[base + 128 + col] = hi; pb[base + 256 + col] = lo;
}

__global__ void sqnorm_kernel(const float* __restrict__ x, int n) {
    int warp = (blockIdx.x * blockDim.x + threadIdx.x) >> 5;
    int lane = threadIdx.x & 31;
    if (warp >= n) return;
    float4 v = ((const float4*)(x + (size_t)warp * DIM))[lane];
    float s = v.x * v.x + v.y * v.y + v.z * v.z + v.w * v.w;
    #pragma unroll
    for (int o = 16; o; o >>= 1) s += __shfl_xor_sync(0xffffffffu, s, o);
    if (lane == 0) g_sq[warp] = s;
}

// ---------------------------------------------------------------------------
// HMMA bf16 GEMM: CTA 128x256, 8 warps of 64x64, K=384, 3-stage cp.async
// ---------------------------------------------------------------------------
__device__ __forceinline__ void load_chunk(uint32_t sb, int stage, int c,
                                           int i0, int j0, int tid) {
    uint32_t s = sb + stage * STAGE_SZ;
    #pragma unroll
    for (int r = 0; r < 4; r++) {                 // A: 1024 uint4
        int idx = tid + r * 256;
        int row = idx >> 3, q = idx & 7;
        const uint4* src = &g_pa[(size_t)(i0 + row) * 48 + c * 8 + q];
        CP_ASYNC16(s + SWZ(row * 128 + q * 16), src);
    }
    #pragma unroll
    for (int r = 0; r < 8; r++) {                 // B: 2048 uint4
        int idx = tid + r * 256;
        int row = idx >> 3, q = idx & 7;
        const uint4* src = &g_pb[(size_t)(j0 + row) * 48 + c * 8 + q];
        CP_ASYNC16(s + OFF_B + SWZ(row * 128 + q * 16), src);
    }
    CP_COMMIT();
}

__global__ __launch_bounds__(256, 1) void hmma_gemm(int n) {
    extern __shared__ __align__(16) char smem[];
    const uint32_t sb = smem_u32(smem);
    const int tid = threadIdx.x;
    const int wid = tid >> 5;
    const int lane = tid & 31;
    const int wm = wid & 1;
    const int wn = wid >> 1;
    const int mr = wm * 64;
    const int nr = wn * 64;

    const int i0 = blockIdx.y * TM;
    const int j0 = blockIdx.x * TN;

    const int row_off = lane & 15;
    const int colh2 = (lane >> 4) * 16;
    const uint32_t aRow = (uint32_t)(mr + row_off) * 128;
    const uint32_t bRow = (uint32_t)(nr + row_off) * 128;

    float acc[4][8][4];
    #pragma unroll
    for (int i = 0; i < 4; i++)
        #pragma unroll
        for (int j = 0; j < 8; j++)
            #pragma unroll
            for (int q = 0; q < 4; q++) acc[i][j][q] = 0.0f;

    load_chunk(sb, 0, 0, i0, j0, tid);
    load_chunk(sb, 1, 1, i0, j0, tid);

    for (int c = 0; c < NCHUNK; c++) {
        if (c + 2 < NCHUNK) {
            load_chunk(sb, (c + 2) % 3, c + 2, i0, j0, tid);
            CP_WAIT(2);
        } else if (c + 1 < NCHUNK) {
            CP_WAIT(1);
        } else {
            CP_WAIT(0);
        }
        __syncthreads();

        uint32_t sA = sb + (c % 3) * STAGE_SZ;
        uint32_t sB = sA + OFF_B;

        #pragma unroll
        for (int ks = 0; ks < 4; ks++) {
            uint32_t colb = ks * 32 + colh2;
            uint32_t aF[4][4], bF[8][2];
            #pragma unroll
            for (int i = 0; i < 4; i++) {
                uint32_t ad = sA + SWZ(aRow + i * 2048 + colb);
                LDSM_X4(aF[i][0], aF[i][1], aF[i][2], aF[i][3], ad);
            }
            #pragma unroll
            for (int jj = 0; jj < 4; jj++) {
                uint32_t r0, r1, r2, r3;
                uint32_t bd = sB + SWZ(bRow + jj * 2048 + colb);
                LDSM_X4(r0, r1, r2, r3, bd);
                bF[2 * jj][0] = r0; bF[2 * jj][1] = r2;
                bF[2 * jj + 1][0] = r1; bF[2 * jj + 1][1] = r3;
            }
            #pragma unroll
            for (int i = 0; i < 4; i++)
                #pragma unroll
                for (int j = 0; j < 8; j++)
                    MMA_BF16(acc[i][j], aF[i], bF[j]);
        }
        __syncthreads();
    }

    const int g = lane >> 2, t = lane & 3;
    #pragma unroll
    for (int i = 0; i < 4; i++) {
        int r0 = i0 + mr + i * 16 + g;
        #pragma unroll
        for (int j = 0; j < 8; j++) {
            int cc = j0 + nr + j * 8 + t * 2;
            float2 v0 = make_float2(acc[i][j][0], acc[i][j][1]);
            float2 v1 = make_float2(acc[i][j][2], acc[i][j][3]);
            *(float2*)(g_dot + (size_t)r0 * n + cc) = v0;
            *(float2*)(g_dot + (size_t)(r0 + 8) * n + cc) = v1;
        }
    }
}

// ---------------------------------------------------------------------------
// per-row epilogue. All transcendentals on the FMA pipe (no MUFU).
// ---------------------------------------------------------------------------
__device__ __forceinline__ float fast_exp_neg(float d) {
    // exp(-d) for d in [0, ~80): 2^t with t = -d*log2(e)
    const float MAGIC = 12582912.0f;           // 1.5 * 2^23
    float r  = fmaf(d, -1.4426950408889634f, MAGIC);
    float fi = r - MAGIC;                       // round(t)
    float f  = fmaf(d, -1.4426950408889634f, -fi);   // t - round(t), [-0.5,0.5]
    float p = 1.3333558146e-3f;
    p = fmaf(p, f, 9.6181291918e-3f);
    p = fmaf(p, f, 5.5504108665e-2f);
    p = fmaf(p, f, 2.4022650696e-1f);
    p = fmaf(p, f, 6.9314718056e-1f);
    p = fmaf(p, f, 1.0f);
    int ebits = (__float_as_int(r) - 0x4B400000) << 23;
    return __int_as_float(__float_as_int(p) + ebits);
}

__device__ __forceinline__ float fast_sqrt(float d2) {
    // d2 * rsqrt(d2), bit-trick seed + 2 Newton iters (rel err ~5e-6)
    float y = __int_as_float(0x5f3759dfu - (__float_as_int(d2) >> 1));
    float h = 0.5f * d2;
    y = y * fmaf(-h, y * y, 1.5f);
    y = y * fmaf(-h, y * y, 1.5f);
    return d2 * y;
}

__global__ __launch_bounds__(256) void row_kernel(int n) {
    const int i = blockIdx.x;
    const int tid = threadIdx.x;
    const float4* __restrict__ row4 = (const float4*)(g_dot + (size_t)i * n);
    const float4* __restrict__ sq4 = (const float4*)g_sq;
    const float sqi = g_sq[i];

    float denom = 0.0f;
    float t8[KNB];                 // ascending; t8[7] = current max
    #pragma unroll
    for (int q = 0; q < KNB; q++) t8[q] = CUDART_INF_F;

    #pragma unroll
    for (int it = 0; it < NPTS / 1024; it++) {
        int j4 = it * 256 + tid;
        float4 dv = row4[j4];
        float4 qv = sq4[j4];
        int jb = j4 * 4;
        #pragma unroll
        for (int e = 0; e < 4; e++) {
            float dot = e == 0 ? dv.x : e == 1 ? dv.y : e == 2 ? dv.z : dv.w;
            float sqj = e == 0 ? qv.x : e == 1 ? qv.y : e == 2 ? qv.z : qv.w;
            int j = jb + e;
            float d2 = fmaxf(fmaf(-2.0f, dot, sqi + sqj), 0.0f);
            float ex = fast_exp_neg(fast_sqrt(d2));   // NaN only when d2==0 (self) -> selected away
            bool self = (j == i);
            denom += self ? 0.0f : ex;
            float v = self ? CUDART_INF_F : d2;
            if (v < t8[KNB - 1]) {
                #pragma unroll
                for (int q = 0; q < KNB; q++) {
                    float lo = fminf(t8[q], v);
                    v = fmaxf(t8[q], v);
                    t8[q] = lo;
                }
            }
        }
    }

    __shared__ float cand[256 * KNB];
    __shared__ float sv[256];
    __shared__ int   si[256];
    __shared__ float s_denom;

    #pragma unroll
    for (int q = 0; q < KNB; q++) cand[tid * KNB + q] = t8[q];

    sv[tid] = denom;
    __syncthreads();
    for (int o = 128; o; o >>= 1) {
        if (tid < o) sv[tid] += sv[tid + o];
        __syncthreads();
    }
    if (tid == 0) s_denom = sv[0];
    __syncthreads();

    float dsum = 0.0f;   // valid on tid 0
    for (int r = 0; r < KNB; r++) {
        float m = CUDART_INF_F; int mi = -1;
        for (int q = tid; q < 256 * KNB; q += 256)
            if (cand[q] < m) { m = cand[q]; mi = q; }
        sv[tid] = m; si[tid] = mi;
        __syncthreads();
        for (int o = 128; o; o >>= 1) {
            if (tid < o && sv[tid + o] < sv[tid]) { sv[tid] = sv[tid + o]; si[tid] = si[tid + o]; }
            __syncthreads();
        }
        if (tid == 0) {
            dsum += sqrtf(fmaxf(sv[0], 0.0f));   // precise for the 8 winners
            cand[si[0]] = CUDART_INF_F;
        }
        __syncthreads();
    }

    if (tid == 0)
        g_loss[i] = dsum * (1.0f / KNB) + logf(s_denom);
}

// ---------------------------------------------------------------------------
__global__ void final_kernel(float* __restrict__ out, int n) {
    __shared__ float sv[256];
    const int tid = threadIdx.x;
    float s = 0.0f;
    for (int i = tid; i < n; i += 256) s += g_loss[i];
    sv[tid] = s;
    __syncthreads();
    for (int o = 128; o; o >>= 1) {
        if (tid < o) sv[tid] += sv[tid + o];
        __syncthreads();
    }
    if (tid == 0) out[0] = sv[0] / (float)n;
}

// ---------------------------------------------------------------------------
extern "C" void kernel_launch(void* const* d_in, const int* in_sizes, int n_in,
                              void* d_out, int out_size) {
    const float* x = (const float*)d_in[0];
    float* out = (float*)d_out;
    const int n = in_sizes[0] / DIM;   // 8192

    cudaFuncSetAttribute(hmma_gemm, cudaFuncAttributeMaxDynamicSharedMemorySize,
                         SMEM_TOTAL);

    pack_kernel<<<(n * DIM) / 256, 256>>>(x);
    sqnorm_kernel<<<(n + 7) / 8, 256>>>(x, n);
    hmma_gemm<<<dim3(n / TN, n / TM), 256, SMEM_TOTAL>>>(n);
    row_kernel<<<n, 256>>>(n);
    final_kernel<<<1, 256>>>(out, n);
}

// round 5
// speedup vs baseline: 3.1914x; 1.5471x over previous
#include <cuda_runtime.h>
#include <cuda_bf16.h>
#include <math.h>
#include <math_constants.h>
#include <cstdint>

#define NPTS 8192
#define DIM  128
#define KNB  8
#define KPACK 256          // bf16 [hi|lo] x [hi|hi]
#define TM   128
#define TN   256
#define NCHUNK 4           // 4 x 64-k chunks
#define NSTRIP 128         // 32 CTA cols x 4 warp strips of 64

// ------------------------- device scratch (no allocs) -----------------------
__device__ float g_sq[NPTS];
__device__ float g_loss[NPTS];
__device__ float g_pden[(size_t)NPTS * NSTRIP];
__device__ float g_cand[(size_t)NPTS * NSTRIP * KNB];
__device__ uint4 g_pa[(size_t)NPTS * 32];   // 32 uint4 = 256 bf16 per row
__device__ uint4 g_pb[(size_t)NPTS * 32];

// ------------------------- helpers ------------------------------------------
__device__ __forceinline__ uint32_t smem_u32(const void* p) {
    uint32_t a;
    asm("{ .reg .u64 t; cvta.to.shared.u64 t, %1; cvt.u32.u64 %0, t; }"
        : "=r"(a) : "l"(p));
    return a;
}
#define SWZ(o) ((o) ^ (((o) >> 3) & 0x70))

#define CP_ASYNC16(dst, src) \
    asm volatile("cp.async.cg.shared.global [%0], [%1], 16;" \
                 :: "r"(dst), "l"(src) : "memory")
#define CP_COMMIT() asm volatile("cp.async.commit_group;" ::: "memory")
#define CP_WAIT(N)  asm volatile("cp.async.wait_group %0;" :: "n"(N) : "memory")

#define LDSM_X4(r0, r1, r2, r3, a) \
    asm volatile("ldmatrix.sync.aligned.m8n8.x4.shared.b16 {%0,%1,%2,%3}, [%4];" \
                 : "=r"(r0), "=r"(r1), "=r"(r2), "=r"(r3) : "r"(a))

#define MMA_BF16(c, a, b) \
    asm volatile("mma.sync.aligned.m16n8k16.row.col.f32.bf16.bf16.f32 " \
                 "{%0,%1,%2,%3}, {%4,%5,%6,%7}, {%8,%9}, {%0,%1,%2,%3};" \
                 : "+f"((c)[0]), "+f"((c)[1]), "+f"((c)[2]), "+f"((c)[3]) \
                 : "r"((a)[0]), "r"((a)[1]), "r"((a)[2]), "r"((a)[3]), \
                   "r"((b)[0]), "r"((b)[1]))

#define STAGE_SZ 49152
#define OFF_B    16384
#define SMEM_TOTAL (3 * STAGE_SZ)

// ---- FMA-pipe transcendentals ----------------------------------------------
__device__ __forceinline__ float fast_exp_neg(float d) {
    const float MAGIC = 12582912.0f;           // 1.5 * 2^23
    float r  = fmaf(d, -1.4426950408889634f, MAGIC);
    float fi = r - MAGIC;
    float f  = fmaf(d, -1.4426950408889634f, -fi);
    float p = 1.3333558146e-3f;
    p = fmaf(p, f, 9.6181291918e-3f);
    p = fmaf(p, f, 5.5504108665e-2f);
    p = fmaf(p, f, 2.4022650696e-1f);
    p = fmaf(p, f, 6.9314718056e-1f);
    p = fmaf(p, f, 1.0f);
    int ebits = (__float_as_int(r) - 0x4B400000) << 23;
    return __int_as_float(__float_as_int(p) + ebits);
}
__device__ __forceinline__ float fast_sqrt(float d2) {
    float y = __int_as_float(0x5f3759dfu - (__float_as_int(d2) >> 1));
    float h = 0.5f * d2;
    y = y * fmaf(-h, y * y, 1.5f);
    y = y * fmaf(-h, y * y, 1.5f);
    return d2 * y;
}

// ---- sorting networks -------------------------------------------------------
__device__ __forceinline__ void cas(float& a, float& b) {
    float lo = fminf(a, b), hi = fmaxf(a, b); a = lo; b = hi;
}
// Batcher odd-even mergesort, 8 elems, 19 CAS
__device__ __forceinline__ void sort8(float* v) {
    cas(v[0],v[1]); cas(v[2],v[3]); cas(v[4],v[5]); cas(v[6],v[7]);
    cas(v[0],v[2]); cas(v[1],v[3]); cas(v[4],v[6]); cas(v[5],v[7]);
    cas(v[1],v[2]); cas(v[5],v[6]);
    cas(v[0],v[4]); cas(v[1],v[5]); cas(v[2],v[6]); cas(v[3],v[7]);
    cas(v[2],v[4]); cas(v[3],v[5]);
    cas(v[1],v[2]); cas(v[3],v[4]); cas(v[5],v[6]);
}
// sort a bitonic 8-seq ascending (12 CAS)
__device__ __forceinline__ void bitonic8(float* v) {
    cas(v[0],v[4]); cas(v[1],v[5]); cas(v[2],v[6]); cas(v[3],v[7]);
    cas(v[0],v[2]); cas(v[1],v[3]); cas(v[4],v[6]); cas(v[5],v[7]);
    cas(v[0],v[1]); cas(v[2],v[3]); cas(v[4],v[5]); cas(v[6],v[7]);
}
// t := smallest 8 of (t ∪ o), both sorted ascending; result sorted
__device__ __forceinline__ void merge8(float* t, const float* o) {
    float m[8];
    #pragma unroll
    for (int q = 0; q < 8; q++) m[q] = fminf(t[q], o[7 - q]);
    bitonic8(m);
    #pragma unroll
    for (int q = 0; q < 8; q++) t[q] = m[q];
}
// cross-lane merge of sorted-8 lists via shfl_xor
__device__ __forceinline__ void merge8_shfl(float* t, int mask) {
    float o[8];
    #pragma unroll
    for (int q = 0; q < 8; q++) o[q] = __shfl_xor_sync(0xffffffffu, t[7 - q], mask);
    #pragma unroll
    for (int q = 0; q < 8; q++) t[q] = fminf(t[q], o[q]);
    bitonic8(t);
}

// ---------------------------------------------------------------------------
__global__ void pack_kernel(const float* __restrict__ x) {
    int t = blockIdx.x * blockDim.x + threadIdx.x;
    int i = t >> 7, col = t & 127;
    float v = x[(size_t)i * DIM + col];
    __nv_bfloat16 hi = __float2bfloat16(v);
    __nv_bfloat16 lo = __float2bfloat16(v - __bfloat162float(hi));
    __nv_bfloat16* pa = (__nv_bfloat16*)g_pa;
    __nv_bfloat16* pb = (__nv_bfloat16*)g_pb;
    size_t base = (size_t)i * KPACK;
    pa[base + col] = hi; pa[base + 128 + col] = lo;
    pb[base + col] = hi; pb[base + 128 + col] = hi;
}

__global__ void sqnorm_kernel(const float* __restrict__ x, int n) {
    int warp = (blockIdx.x * blockDim.x + threadIdx.x) >> 5;
    int lane = threadIdx.x & 31;
    if (warp >= n) return;
    float4 v = ((const float4*)(x + (size_t)warp * DIM))[lane];
    float s = v.x * v.x + v.y * v.y + v.z * v.z + v.w * v.w;
    #pragma unroll
    for (int o = 16; o; o >>= 1) s += __shfl_xor_sync(0xffffffffu, s, o);
    if (lane == 0) g_sq[warp] = s;
}

// ---------------------------------------------------------------------------
// Fused GEMM + epilogue: CTA 128x256, warps 2x4 of 64x64, K=256.
// Per (row, 64-col strip): writes partial denom + sorted top-8 d2 candidates.
// ---------------------------------------------------------------------------
__device__ __forceinline__ void load_chunk(uint32_t sb, int stage, int c,
                                           int i0, int j0, int tid) {
    uint32_t s = sb + stage * STAGE_SZ;
    #pragma unroll
    for (int r = 0; r < 4; r++) {                 // A: 1024 uint4
        int idx = tid + r * 256;
        int row = idx >> 3, q = idx & 7;
        const uint4* src = &g_pa[(size_t)(i0 + row) * 32 + c * 8 + q];
        CP_ASYNC16(s + SWZ(row * 128 + q * 16), src);
    }
    #pragma unroll
    for (int r = 0; r < 8; r++) {                 // B: 2048 uint4
        int idx = tid + r * 256;
        int row = idx >> 3, q = idx & 7;
        const uint4* src = &g_pb[(size_t)(j0 + row) * 32 + c * 8 + q];
        CP_ASYNC16(s + OFF_B + SWZ(row * 128 + q * 16), src);
    }
    CP_COMMIT();
}

__global__ __launch_bounds__(256, 1) void fused_gemm(int n) {
    extern __shared__ __align__(16) char smem[];
    const uint32_t sb = smem_u32(smem);
    const int tid = threadIdx.x;
    const int wid = tid >> 5;
    const int lane = tid & 31;
    const int wm = wid & 1;
    const int wn = wid >> 1;
    const int mr = wm * 64;
    const int nr = wn * 64;

    const int i0 = blockIdx.y * TM;
    const int j0 = blockIdx.x * TN;

    const int row_off = lane & 15;
    const int colh2 = (lane >> 4) * 16;
    const uint32_t aRow = (uint32_t)(mr + row_off) * 128;
    const uint32_t bRow = (uint32_t)(nr + row_off) * 128;

    float acc[4][8][4];
    #pragma unroll
    for (int i = 0; i < 4; i++)
        #pragma unroll
        for (int j = 0; j < 8; j++)
            #pragma unroll
            for (int q = 0; q < 4; q++) acc[i][j][q] = 0.0f;

    load_chunk(sb, 0, 0, i0, j0, tid);
    load_chunk(sb, 1, 1, i0, j0, tid);

    for (int c = 0; c < NCHUNK; c++) {
        if (c + 2 < NCHUNK) {
            load_chunk(sb, (c + 2) % 3, c + 2, i0, j0, tid);
            CP_WAIT(2);
        } else if (c + 1 < NCHUNK) {
            CP_WAIT(1);
        } else {
            CP_WAIT(0);
        }
        __syncthreads();

        uint32_t sA = sb + (c % 3) * STAGE_SZ;
        uint32_t sB = sA + OFF_B;

        #pragma unroll
        for (int ks = 0; ks < 4; ks++) {
            uint32_t colb = ks * 32 + colh2;
            uint32_t aF[4][4], bF[8][2];
            #pragma unroll
            for (int i = 0; i < 4; i++) {
                uint32_t ad = sA + SWZ(aRow + i * 2048 + colb);
                LDSM_X4(aF[i][0], aF[i][1], aF[i][2], aF[i][3], ad);
            }
            #pragma unroll
            for (int jj = 0; jj < 4; jj++) {
                uint32_t r0, r1, r2, r3;
                uint32_t bd = sB + SWZ(bRow + jj * 2048 + colb);
                LDSM_X4(r0, r1, r2, r3, bd);
                bF[2 * jj][0] = r0; bF[2 * jj][1] = r2;
                bF[2 * jj + 1][0] = r1; bF[2 * jj + 1][1] = r3;
            }
            #pragma unroll
            for (int i = 0; i < 4; i++)
                #pragma unroll
                for (int j = 0; j < 8; j++)
                    MMA_BF16(acc[i][j], aF[i], bF[j]);
        }
        __syncthreads();
    }

    // ---------------- fused epilogue ----------------
    const int g = lane >> 2, t = lane & 3;
    const int strip = blockIdx.x * 4 + wn;
    const int scol = j0 + nr + t * 2;         // this lane's base column

    float sqc[16];
    #pragma unroll
    for (int j = 0; j < 8; j++) {
        sqc[2 * j]     = g_sq[scol + j * 8];
        sqc[2 * j + 1] = g_sq[scol + j * 8 + 1];
    }

    #pragma unroll
    for (int i = 0; i < 4; i++) {
        #pragma unroll
        for (int h = 0; h < 2; h++) {
            const int rg = i0 + mr + i * 16 + h * 8 + g;
            const float sqi = g_sq[rg];
            float v16[16];
            float den = 0.0f;
            #pragma unroll
            for (int j = 0; j < 8; j++) {
                #pragma unroll
                for (int e = 0; e < 2; e++) {
                    float dot = acc[i][j][h * 2 + e];
                    int cg = scol + j * 8 + e;
                    float d2 = fmaxf(fmaf(-2.0f, dot, sqi + sqc[2 * j + e]), 0.0f);
                    bool self = (cg == rg);
                    float ex = fast_exp_neg(fast_sqrt(d2));
                    den += self ? 0.0f : ex;
                    v16[j * 2 + e] = self ? CUDART_INF_F : d2;
                }
            }
            // denom over the 4 lanes sharing this row (t bits = lane bits 0-1)
            den += __shfl_xor_sync(0xffffffffu, den, 1);
            den += __shfl_xor_sync(0xffffffffu, den, 2);
            // top-8: sort halves, merge, then merge across t-lanes
            sort8(v16); sort8(v16 + 8);
            merge8(v16, v16 + 8);
            merge8_shfl(v16, 1);
            merge8_shfl(v16, 2);
            if (t == 0) {
                g_pden[(size_t)rg * NSTRIP + strip] = den;
                float4* dst = (float4*)&g_cand[((size_t)rg * NSTRIP + strip) * KNB];
                dst[0] = make_float4(v16[0], v16[1], v16[2], v16[3]);
                dst[1] = make_float4(v16[4], v16[5], v16[6], v16[7]);
            }
        }
    }
}

// ---------------------------------------------------------------------------
// merge kernel: one warp per row. 128 sorted 8-lists -> global top-8 + loss.
// ---------------------------------------------------------------------------
__global__ __launch_bounds__(256) void merge_kernel(int n) {
    const int row = (blockIdx.x * 256 + threadIdx.x) >> 5;
    const int lane = threadIdx.x & 31;
    if (row >= n) return;

    // each lane: 4 sorted lists = 32 contiguous floats
    const float4* src = (const float4*)(g_cand + (size_t)row * NSTRIP * KNB) + lane * 8;
    float l[32];
    #pragma unroll
    for (int q = 0; q < 8; q++) {
        float4 v = src[q];
        l[q * 4] = v.x; l[q * 4 + 1] = v.y; l[q * 4 + 2] = v.z; l[q * 4 + 3] = v.w;
    }
    merge8(l, l + 8);
    merge8(l + 16, l + 24);
    merge8(l, l + 16);
    merge8_shfl(l, 1);
    merge8_shfl(l, 2);
    merge8_shfl(l, 4);
    merge8_shfl(l, 8);
    merge8_shfl(l, 16);

    // deterministic denom: fixed in-lane order + fixed shfl tree
    const float4* dsrc = (const float4*)(g_pden + (size_t)row * NSTRIP);
    float4 dv = dsrc[lane];
    float den = (dv.x + dv.y) + (dv.z + dv.w);
    #pragma unroll
    for (int m = 1; m < 32; m <<= 1) den += __shfl_xor_sync(0xffffffffu, den, m);

    if (lane == 0) {
        float ds = 0.0f;
        #pragma unroll
        for (int q = 0; q < KNB; q++) ds += sqrtf(fmaxf(l[q], 0.0f));
        g_loss[row] = ds * (1.0f / KNB) + logf(den);
    }
}

// ---------------------------------------------------------------------------
__global__ void final_kernel(float* __restrict__ out, int n) {
    __shared__ float sv[256];
    const int tid = threadIdx.x;
    float s = 0.0f;
    for (int i = tid; i < n; i += 256) s += g_loss[i];
    sv[tid] = s;
    __syncthreads();
    for (int o = 128; o; o >>= 1) {
        if (tid < o) sv[tid] += sv[tid + o];
        __syncthreads();
    }
    if (tid == 0) out[0] = sv[0] / (float)n;
}

// ---------------------------------------------------------------------------
extern "C" void kernel_launch(void* const* d_in, const int* in_sizes, int n_in,
                              void* d_out, int out_size) {
    const float* x = (const float*)d_in[0];
    float* out = (float*)d_out;
    const int n = in_sizes[0] / DIM;   // 8192

    cudaFuncSetAttribute(fused_gemm, cudaFuncAttributeMaxDynamicSharedMemorySize,
                         SMEM_TOTAL);

    pack_kernel<<<(n * DIM) / 256, 256>>>(x);
    sqnorm_kernel<<<(n + 7) / 8, 256>>>(x, n);
    fused_gemm<<<dim3(n / TN, n / TM), 256, SMEM_TOTAL>>>(n);
    merge_kernel<<<(n * 32) / 256, 256>>>(n);
    final_kernel<<<1, 256>>>(out, n);
}

// round 6
// speedup vs baseline: 3.8220x; 1.1976x over previous
#include <cuda_runtime.h>
#include <cuda_bf16.h>
#include <math.h>
#include <math_constants.h>
#include <cstdint>

#define NPTS 8192
#define DIM  128
#define KNB  8
#define KPACK 256          // bf16 [hi|lo] x [hi|hi]
#define NB   64            // 8192/128 blocks per side
#define NCHUNK 4           // 4 x 64-k chunks
#define SLOTS 384          // per row: 256 row-side + 128 col-side
#define COLBASE 256

// ------------------------- device scratch (no allocs) -----------------------
__device__ float g_sq[NPTS];
__device__ float g_loss[NPTS];
__device__ float g_pden[(size_t)NPTS * SLOTS];
__device__ float g_cand[(size_t)NPTS * SLOTS * KNB];
__device__ uint4 g_pa[(size_t)NPTS * 32];   // 32 uint4 = 256 bf16 per row
__device__ uint4 g_pb[(size_t)NPTS * 32];

// ------------------------- helpers ------------------------------------------
__device__ __forceinline__ uint32_t smem_u32(const void* p) {
    uint32_t a;
    asm("{ .reg .u64 t; cvta.to.shared.u64 t, %1; cvt.u32.u64 %0, t; }"
        : "=r"(a) : "l"(p));
    return a;
}
#define SWZ(o) ((o) ^ (((o) >> 3) & 0x70))

#define CP_ASYNC16(dst, src) \
    asm volatile("cp.async.cg.shared.global [%0], [%1], 16;" \
                 :: "r"(dst), "l"(src) : "memory")
#define CP_COMMIT() asm volatile("cp.async.commit_group;" ::: "memory")
#define CP_WAIT(N)  asm volatile("cp.async.wait_group %0;" :: "n"(N) : "memory")

#define LDSM_X4(r0, r1, r2, r3, a) \
    asm volatile("ldmatrix.sync.aligned.m8n8.x4.shared.b16 {%0,%1,%2,%3}, [%4];" \
                 : "=r"(r0), "=r"(r1), "=r"(r2), "=r"(r3) : "r"(a))

#define MMA_BF16(c, a, b) \
    asm volatile("mma.sync.aligned.m16n8k16.row.col.f32.bf16.bf16.f32 " \
                 "{%0,%1,%2,%3}, {%4,%5,%6,%7}, {%8,%9}, {%0,%1,%2,%3};" \
                 : "+f"((c)[0]), "+f"((c)[1]), "+f"((c)[2]), "+f"((c)[3]) \
                 : "r"((a)[0]), "r"((a)[1]), "r"((a)[2]), "r"((a)[3]), \
                   "r"((b)[0]), "r"((b)[1]))

// stage: A 16KB + B 16KB; 3 stages = 96KB
#define STAGE_SZ 32768
#define OFF_B    16384
#define SMEM_TOTAL (3 * STAGE_SZ)

// ---- FMA-pipe transcendentals ----------------------------------------------
__device__ __forceinline__ float fast_exp_neg(float d) {
    const float MAGIC = 12582912.0f;           // 1.5 * 2^23
    float r  = fmaf(d, -1.4426950408889634f, MAGIC);
    float fi = r - MAGIC;
    float f  = fmaf(d, -1.4426950408889634f, -fi);
    float p = 1.3333558146e-3f;
    p = fmaf(p, f, 9.6181291918e-3f);
    p = fmaf(p, f, 5.5504108665e-2f);
    p = fmaf(p, f, 2.4022650696e-1f);
    p = fmaf(p, f, 6.9314718056e-1f);
    p = fmaf(p, f, 1.0f);
    int ebits = (__float_as_int(r) - 0x4B400000) << 23;
    return __int_as_float(__float_as_int(p) + ebits);
}
__device__ __forceinline__ float fast_sqrt(float d2) {
    float y = __int_as_float(0x5f3759dfu - (__float_as_int(d2) >> 1));
    float h = 0.5f * d2;
    y = y * fmaf(-h, y * y, 1.5f);
    y = y * fmaf(-h, y * y, 1.5f);
    return d2 * y;
}

// ---- sorting networks -------------------------------------------------------
__device__ __forceinline__ void cas(float& a, float& b) {
    float lo = fminf(a, b), hi = fmaxf(a, b); a = lo; b = hi;
}
__device__ __forceinline__ void sort8(float* v) {
    cas(v[0],v[1]); cas(v[2],v[3]); cas(v[4],v[5]); cas(v[6],v[7]);
    cas(v[0],v[2]); cas(v[1],v[3]); cas(v[4],v[6]); cas(v[5],v[7]);
    cas(v[1],v[2]); cas(v[5],v[6]);
    cas(v[0],v[4]); cas(v[1],v[5]); cas(v[2],v[6]); cas(v[3],v[7]);
    cas(v[2],v[4]); cas(v[3],v[5]);
    cas(v[1],v[2]); cas(v[3],v[4]); cas(v[5],v[6]);
}
__device__ __forceinline__ void bitonic8(float* v) {
    cas(v[0],v[4]); cas(v[1],v[5]); cas(v[2],v[6]); cas(v[3],v[7]);
    cas(v[0],v[2]); cas(v[1],v[3]); cas(v[4],v[6]); cas(v[5],v[7]);
    cas(v[0],v[1]); cas(v[2],v[3]); cas(v[4],v[5]); cas(v[6],v[7]);
}
__device__ __forceinline__ void merge8(float* t, const float* o) {
    float m[8];
    #pragma unroll
    for (int q = 0; q < 8; q++) m[q] = fminf(t[q], o[7 - q]);
    bitonic8(m);
    #pragma unroll
    for (int q = 0; q < 8; q++) t[q] = m[q];
}
__device__ __forceinline__ void merge8_shfl(float* t, int mask) {
    float o[8];
    #pragma unroll
    for (int q = 0; q < 8; q++) o[q] = __shfl_xor_sync(0xffffffffu, t[7 - q], mask);
    #pragma unroll
    for (int q = 0; q < 8; q++) t[q] = fminf(t[q], o[q]);
    bitonic8(t);
}

// ---------------------------------------------------------------------------
__global__ void pack_kernel(const float* __restrict__ x) {
    int t = blockIdx.x * blockDim.x + threadIdx.x;
    int i = t >> 7, col = t & 127;
    float v = x[(size_t)i * DIM + col];
    __nv_bfloat16 hi = __float2bfloat16(v);
    __nv_bfloat16 lo = __float2bfloat16(v - __bfloat162float(hi));
    __nv_bfloat16* pa = (__nv_bfloat16*)g_pa;
    __nv_bfloat16* pb = (__nv_bfloat16*)g_pb;
    size_t base = (size_t)i * KPACK;
    pa[base + col] = hi; pa[base + 128 + col] = lo;
    pb[base + col] = hi; pb[base + 128 + col] = hi;
}

__global__ void sqnorm_kernel(const float* __restrict__ x, int n) {
    int warp = (blockIdx.x * blockDim.x + threadIdx.x) >> 5;
    int lane = threadIdx.x & 31;
    if (warp >= n) return;
    float4 v = ((const float4*)(x + (size_t)warp * DIM))[lane];
    float s = v.x * v.x + v.y * v.y + v.z * v.z + v.w * v.w;
    #pragma unroll
    for (int o = 16; o; o >>= 1) s += __shfl_xor_sync(0xffffffffu, s, o);
    if (lane == 0) g_sq[warp] = s;
}

// ---------------------------------------------------------------------------
// Symmetric fused GEMM: 128x128 tiles over upper triangle, warps 2(m)x4(n)
// of 64x32. Emits row-side stats always; col-side stats for off-diag tiles.
// ---------------------------------------------------------------------------
__device__ __forceinline__ void load_chunk(uint32_t sb, int stage, int c,
                                           int i0, int j0, int tid) {
    uint32_t s = sb + stage * STAGE_SZ;
    #pragma unroll
    for (int r = 0; r < 4; r++) {                 // A: 1024 uint4
        int idx = tid + r * 256;
        int row = idx >> 3, q = idx & 7;
        const uint4* src = &g_pa[(size_t)(i0 + row) * 32 + c * 8 + q];
        CP_ASYNC16(s + SWZ(row * 128 + q * 16), src);
    }
    #pragma unroll
    for (int r = 0; r < 4; r++) {                 // B: 1024 uint4
        int idx = tid + r * 256;
        int row = idx >> 3, q = idx & 7;
        const uint4* src = &g_pb[(size_t)(j0 + row) * 32 + c * 8 + q];
        CP_ASYNC16(s + OFF_B + SWZ(row * 128 + q * 16), src);
    }
    CP_COMMIT();
}

__global__ __launch_bounds__(256, 1) void fused_gemm(int n) {
    extern __shared__ __align__(16) char smem[];
    const uint32_t sb = smem_u32(smem);
    const int tid = threadIdx.x;
    const int wid = tid >> 5;
    const int lane = tid & 31;
    const int wm = wid & 1;          // 64-row half
    const int wn = wid >> 1;         // 32-col strip
    const int mr = wm * 64;
    const int nr = wn * 32;

    // decode triangular tile
    int rem = blockIdx.x, bi = 0;
    while (rem >= NB - bi) { rem -= NB - bi; bi++; }
    const int bj = bi + rem;
    const int i0 = bi * 128, j0 = bj * 128;
    const bool diag = (bi == bj);

    const int row_off = lane & 15;
    const int colh2 = (lane >> 4) * 16;
    const uint32_t aRow = (uint32_t)(mr + row_off) * 128;
    const uint32_t bRow = (uint32_t)(nr + row_off) * 128;

    float acc[4][4][4];
    #pragma unroll
    for (int i = 0; i < 4; i++)
        #pragma unroll
        for (int j = 0; j < 4; j++)
            #pragma unroll
            for (int q = 0; q < 4; q++) acc[i][j][q] = 0.0f;

    load_chunk(sb, 0, 0, i0, j0, tid);
    load_chunk(sb, 1, 1, i0, j0, tid);

    for (int c = 0; c < NCHUNK; c++) {
        if (c + 2 < NCHUNK) {
            load_chunk(sb, (c + 2) % 3, c + 2, i0, j0, tid);
            CP_WAIT(2);
        } else if (c + 1 < NCHUNK) {
            CP_WAIT(1);
        } else {
            CP_WAIT(0);
        }
        __syncthreads();

        uint32_t sA = sb + (c % 3) * STAGE_SZ;
        uint32_t sB = sA + OFF_B;

        #pragma unroll
        for (int ks = 0; ks < 4; ks++) {
            uint32_t colb = ks * 32 + colh2;
            uint32_t aF[4][4], bF[4][2];
            #pragma unroll
            for (int i = 0; i < 4; i++) {
                uint32_t ad = sA + SWZ(aRow + i * 2048 + colb);
                LDSM_X4(aF[i][0], aF[i][1], aF[i][2], aF[i][3], ad);
            }
            #pragma unroll
            for (int jj = 0; jj < 2; jj++) {
                uint32_t r0, r1, r2, r3;
                uint32_t bd = sB + SWZ(bRow + jj * 2048 + colb);
                LDSM_X4(r0, r1, r2, r3, bd);
                bF[2 * jj][0] = r0; bF[2 * jj][1] = r2;
                bF[2 * jj + 1][0] = r1; bF[2 * jj + 1][1] = r3;
            }
            #pragma unroll
            for (int i = 0; i < 4; i++)
                #pragma unroll
                for (int j = 0; j < 4; j++)
                    MMA_BF16(acc[i][j], aF[i], bF[j]);
        }
        __syncthreads();
    }

    // ---------------- fused epilogue ----------------
    const int g = lane >> 2, t = lane & 3;
    const int scol = j0 + nr + t * 2;

    float sqc[8], colden[8], colv[8][8];
    #pragma unroll
    for (int j = 0; j < 4; j++) {
        #pragma unroll
        for (int e = 0; e < 2; e++) {
            sqc[j * 2 + e] = g_sq[scol + j * 8 + e];
            colden[j * 2 + e] = 0.0f;
        }
    }

    const int rslot = (bj - bi) * 4 + wn;      // row-side slot index
    #pragma unroll
    for (int i = 0; i < 4; i++) {
        #pragma unroll
        for (int h = 0; h < 2; h++) {
            const int rg = i0 + mr + i * 16 + h * 8 + g;
            const float sqi = g_sq[rg];
            float v8[8];
            float den = 0.0f;
            #pragma unroll
            for (int j = 0; j < 4; j++) {
                #pragma unroll
                for (int e = 0; e < 2; e++) {
                    const int je = j * 2 + e;
                    float dot = acc[i][j][h * 2 + e];
                    int cg = scol + j * 8 + e;
                    float d2 = fmaxf(fmaf(-2.0f, dot, sqi + sqc[je]), 0.0f);
                    bool self = diag && (cg == rg);
                    float ex = fast_exp_neg(fast_sqrt(d2));
                    ex = self ? 0.0f : ex;
                    den += ex;
                    colden[je] += ex;
                    float v = self ? CUDART_INF_F : d2;
                    v8[je] = v;
                    colv[je][i * 2 + h] = v;
                }
            }
            den += __shfl_xor_sync(0xffffffffu, den, 1);
            den += __shfl_xor_sync(0xffffffffu, den, 2);
            sort8(v8);
            merge8_shfl(v8, 1);
            merge8_shfl(v8, 2);
            if (t == 0) {
                g_pden[(size_t)rg * SLOTS + rslot] = den;
                float4* dst = (float4*)&g_cand[((size_t)rg * SLOTS + rslot) * KNB];
                dst[0] = make_float4(v8[0], v8[1], v8[2], v8[3]);
                dst[1] = make_float4(v8[4], v8[5], v8[6], v8[7]);
            }
        }
    }

    if (!diag) {
        const int cslot = COLBASE + bi * 2 + wm;
        #pragma unroll
        for (int je = 0; je < 8; je++) {
            sort8(colv[je]);
            merge8_shfl(colv[je], 4);
            merge8_shfl(colv[je], 8);
            merge8_shfl(colv[je], 16);
            float cd = colden[je];
            cd += __shfl_xor_sync(0xffffffffu, cd, 4);
            cd += __shfl_xor_sync(0xffffffffu, cd, 8);
            cd += __shfl_xor_sync(0xffffffffu, cd, 16);
            colden[je] = cd;
        }
        if (g == 0) {
            #pragma unroll
            for (int j = 0; j < 4; j++) {
                #pragma unroll
                for (int e = 0; e < 2; e++) {
                    const int je = j * 2 + e;
                    const int cg = scol + j * 8 + e;
                    g_pden[(size_t)cg * SLOTS + cslot] = colden[je];
                    float4* dst = (float4*)&g_cand[((size_t)cg * SLOTS + cslot) * KNB];
                    dst[0] = make_float4(colv[je][0], colv[je][1], colv[je][2], colv[je][3]);
                    dst[1] = make_float4(colv[je][4], colv[je][5], colv[je][6], colv[je][7]);
                }
            }
        }
    }
}

// ---------------------------------------------------------------------------
// merge kernel: one warp per row; reads only the valid slots.
// ---------------------------------------------------------------------------
__global__ __launch_bounds__(256) void merge_kernel(int n) {
    const int row = (blockIdx.x * 256 + threadIdx.x) >> 5;
    const int lane = threadIdx.x & 31;
    if (row >= n) return;
    const int bi = row >> 7;
    const int nrow = (NB - bi) * 4;
    const int ntot = nrow + 2 * bi;

    float l8[8];
    #pragma unroll
    for (int q = 0; q < 8; q++) l8[q] = CUDART_INF_F;
    float den = 0.0f;

    for (int s = lane; s < ntot; s += 32) {
        int slot = (s < nrow) ? s : (COLBASE + (s - nrow));
        const float4* src = (const float4*)&g_cand[((size_t)row * SLOTS + slot) * KNB];
        float o[8];
        float4 a = src[0], b = src[1];
        o[0] = a.x; o[1] = a.y; o[2] = a.z; o[3] = a.w;
        o[4] = b.x; o[5] = b.y; o[6] = b.z; o[7] = b.w;
        merge8(l8, o);
        den += g_pden[(size_t)row * SLOTS + slot];
    }
    merge8_shfl(l8, 1);
    merge8_shfl(l8, 2);
    merge8_shfl(l8, 4);
    merge8_shfl(l8, 8);
    merge8_shfl(l8, 16);
    #pragma unroll
    for (int m = 1; m < 32; m <<= 1) den += __shfl_xor_sync(0xffffffffu, den, m);

    if (lane == 0) {
        float ds = 0.0f;
        #pragma unroll
        for (int q = 0; q < KNB; q++) ds += sqrtf(fmaxf(l8[q], 0.0f));
        g_loss[row] = ds * (1.0f / KNB) + logf(den);
    }
}

// ---------------------------------------------------------------------------
__global__ void final_kernel(float* __restrict__ out, int n) {
    __shared__ float sv[256];
    const int tid = threadIdx.x;
    float s = 0.0f;
    for (int i = tid; i < n; i += 256) s += g_loss[i];
    sv[tid] = s;
    __syncthreads();
    for (int o = 128; o; o >>= 1) {
        if (tid < o) sv[tid] += sv[tid + o];
        __syncthreads();
    }
    if (tid == 0) out[0] = sv[0] / (float)n;
}

// ---------------------------------------------------------------------------
extern "C" void kernel_launch(void* const* d_in, const int* in_sizes, int n_in,
                              void* d_out, int out_size) {
    const float* x = (const float*)d_in[0];
    float* out = (float*)d_out;
    const int n = in_sizes[0] / DIM;   // 8192
    const int tri = NB * (NB + 1) / 2; // 2080

    cudaFuncSetAttribute(fused_gemm, cudaFuncAttributeMaxDynamicSharedMemorySize,
                         SMEM_TOTAL);

    pack_kernel<<<(n * DIM) / 256, 256>>>(x);
    sqnorm_kernel<<<(n + 7) / 8, 256>>>(x, n);
    fused_gemm<<<tri, 256, SMEM_TOTAL>>>(n);
    merge_kernel<<<(n * 32) / 256, 256>>>(n);
    final_kernel<<<1, 256>>>(out, n);
}

// round 8
// speedup vs baseline: 4.0346x; 1.0556x over previous
#include <cuda_runtime.h>
#include <cuda_bf16.h>
#include <math.h>
#include <math_constants.h>
#include <cstdint>

#define NPTS 8192
#define DIM  128
#define KNB  8
#define NB   64            // 8192/128 blocks per side
#define NCHUNK 4           // 4 x 64-k chunks (A: [hi|lo] K=256; B hi reused twice)
#define SLOTS 384          // per row: 256 row-side + 128 col-side
#define COLBASE 256

// ------------------------- device scratch (no allocs) -----------------------
__device__ float g_sq[NPTS];
__device__ float g_loss[NPTS];
__device__ float g_pden[(size_t)NPTS * SLOTS];
__device__ float g_cand[(size_t)NPTS * SLOTS * KNB];
__device__ uint4 g_pa[(size_t)NPTS * 32];   // 256 bf16 per row  [hi|lo]
__device__ uint4 g_pb[(size_t)NPTS * 16];   // 128 bf16 per row  [hi]

// ------------------------- helpers ------------------------------------------
__device__ __forceinline__ uint32_t smem_u32(const void* p) {
    uint32_t a;
    asm("{ .reg .u64 t; cvta.to.shared.u64 t, %1; cvt.u32.u64 %0, t; }"
        : "=r"(a) : "l"(p));
    return a;
}
#define SWZ(o) ((o) ^ (((o) >> 3) & 0x70))

#define CP_ASYNC16(dst, src) \
    asm volatile("cp.async.cg.shared.global [%0], [%1], 16;" \
                 :: "r"(dst), "l"(src) : "memory")
#define CP_COMMIT() asm volatile("cp.async.commit_group;" ::: "memory")
#define CP_WAIT(N)  asm volatile("cp.async.wait_group %0;" :: "n"(N) : "memory")

#define LDSM_X4(r0, r1, r2, r3, a) \
    asm volatile("ldmatrix.sync.aligned.m8n8.x4.shared.b16 {%0,%1,%2,%3}, [%4];" \
                 : "=r"(r0), "=r"(r1), "=r"(r2), "=r"(r3) : "r"(a))

#define MMA_BF16(c, a, b) \
    asm volatile("mma.sync.aligned.m16n8k16.row.col.f32.bf16.bf16.f32 " \
                 "{%0,%1,%2,%3}, {%4,%5,%6,%7}, {%8,%9}, {%0,%1,%2,%3};" \
                 : "+f"((c)[0]), "+f"((c)[1]), "+f"((c)[2]), "+f"((c)[3]) \
                 : "r"((a)[0]), "r"((a)[1]), "r"((a)[2]), "r"((a)[3]), \
                   "r"((b)[0]), "r"((b)[1]))

// SMEM: B resident 32KB at 0; A 3 stages x 16KB at 32KB. Total 80KB.
#define OFF_A    32768
#define A_STAGE  16384
#define SMEM_TOTAL (32768 + 3 * 16384)

// ---- MUFU transcendentals ---------------------------------------------------
__device__ __forceinline__ float rsqrt_ap(float x) {
    float y; asm("rsqrt.approx.f32 %0, %1;" : "=f"(y) : "f"(x)); return y;
}
__device__ __forceinline__ float ex2_ap(float x) {
    float y; asm("ex2.approx.f32 %0, %1;" : "=f"(y) : "f"(x)); return y;
}

// ---- sorting networks -------------------------------------------------------
__device__ __forceinline__ void cas(float& a, float& b) {
    float lo = fminf(a, b), hi = fmaxf(a, b); a = lo; b = hi;
}
__device__ __forceinline__ void sort8(float* v) {
    cas(v[0],v[1]); cas(v[2],v[3]); cas(v[4],v[5]); cas(v[6],v[7]);
    cas(v[0],v[2]); cas(v[1],v[3]); cas(v[4],v[6]); cas(v[5],v[7]);
    cas(v[1],v[2]); cas(v[5],v[6]);
    cas(v[0],v[4]); cas(v[1],v[5]); cas(v[2],v[6]); cas(v[3],v[7]);
    cas(v[2],v[4]); cas(v[3],v[5]);
    cas(v[1],v[2]); cas(v[3],v[4]); cas(v[5],v[6]);
}
__device__ __forceinline__ void bitonic8(float* v) {
    cas(v[0],v[4]); cas(v[1],v[5]); cas(v[2],v[6]); cas(v[3],v[7]);
    cas(v[0],v[2]); cas(v[1],v[3]); cas(v[4],v[6]); cas(v[5],v[7]);
    cas(v[0],v[1]); cas(v[2],v[3]); cas(v[4],v[5]); cas(v[6],v[7]);
}
__device__ __forceinline__ void merge8(float* t, const float* o) {
    float m[8];
    #pragma unroll
    for (int q = 0; q < 8; q++) m[q] = fminf(t[q], o[7 - q]);
    bitonic8(m);
    #pragma unroll
    for (int q = 0; q < 8; q++) t[q] = m[q];
}
__device__ __forceinline__ void merge8_shfl(float* t, int mask) {
    float o[8];
    #pragma unroll
    for (int q = 0; q < 8; q++) o[q] = __shfl_xor_sync(0xffffffffu, t[7 - q], mask);
    #pragma unroll
    for (int q = 0; q < 8; q++) t[q] = fminf(t[q], o[q]);
    bitonic8(t);
}

// ---------------------------------------------------------------------------
__global__ void pack_kernel(const float* __restrict__ x) {
    int t = blockIdx.x * blockDim.x + threadIdx.x;
    int i = t >> 7, col = t & 127;
    float v = x[(size_t)i * DIM + col];
    __nv_bfloat16 hi = __float2bfloat16(v);
    __nv_bfloat16 lo = __float2bfloat16(v - __bfloat162float(hi));
    __nv_bfloat16* pa = (__nv_bfloat16*)g_pa;
    __nv_bfloat16* pb = (__nv_bfloat16*)g_pb;
    pa[(size_t)i * 256 + col] = hi;
    pa[(size_t)i * 256 + 128 + col] = lo;
    pb[(size_t)i * 128 + col] = hi;
}

__global__ void sqnorm_kernel(const float* __restrict__ x, int n) {
    int warp = (blockIdx.x * blockDim.x + threadIdx.x) >> 5;
    int lane = threadIdx.x & 31;
    if (warp >= n) return;
    float4 v = ((const float4*)(x + (size_t)warp * DIM))[lane];
    float s = v.x * v.x + v.y * v.y + v.z * v.z + v.w * v.w;
    #pragma unroll
    for (int o = 16; o; o >>= 1) s += __shfl_xor_sync(0xffffffffu, s, o);
    if (lane == 0) g_sq[warp] = s;
}

// ---------------------------------------------------------------------------
// Symmetric fused GEMM: 128x128 tiles over upper triangle, warps 2(m)x4(n)
// of 64x32. B (hi only) fully SMEM-resident; A 3-stage pipelined.
// ---------------------------------------------------------------------------
__device__ __forceinline__ void load_chunk_A(uint32_t sb, int stage, int c,
                                             int i0, int tid) {
    uint32_t s = sb + OFF_A + stage * A_STAGE;
    #pragma unroll
    for (int r = 0; r < 4; r++) {                 // 1024 uint4
        int idx = tid + r * 256;
        int row = idx >> 3, q = idx & 7;
        const uint4* src = &g_pa[(size_t)(i0 + row) * 32 + c * 8 + q];
        CP_ASYNC16(s + SWZ(row * 128 + q * 16), src);
    }
    CP_COMMIT();
}

__global__ __launch_bounds__(256, 1) void fused_gemm(int n) {
    extern __shared__ __align__(16) char smem[];
    const uint32_t sb = smem_u32(smem);
    const int tid = threadIdx.x;
    const int wid = tid >> 5;
    const int lane = tid & 31;
    const int wm = wid & 1;          // 64-row half
    const int wn = wid >> 1;         // 32-col strip
    const int mr = wm * 64;
    const int nr = wn * 32;

    int rem = blockIdx.x, bi = 0;
    while (rem >= NB - bi) { rem -= NB - bi; bi++; }
    const int bj = bi + rem;
    const int i0 = bi * 128, j0 = bj * 128;
    const bool diag = (bi == bj);

    // prologue: B resident (2 x 64-k chunks = 2048 uint4), then A0, A1
    #pragma unroll
    for (int r = 0; r < 8; r++) {
        int idx = tid + r * 256;
        int kc = idx >> 10, w = idx & 1023;
        int row = w >> 3, q = w & 7;
        const uint4* src = &g_pb[(size_t)(j0 + row) * 16 + kc * 8 + q];
        CP_ASYNC16(sb + kc * 16384 + SWZ(row * 128 + q * 16), src);
    }
    CP_COMMIT();
    load_chunk_A(sb, 0, 0, i0, tid);
    load_chunk_A(sb, 1, 1, i0, tid);

    const int row_off = lane & 15;
    const int colh2 = (lane >> 4) * 16;
    const uint32_t aRow = (uint32_t)(mr + row_off) * 128;
    const uint32_t bRow = (uint32_t)(nr + row_off) * 128;

    float acc[4][4][4];
    #pragma unroll
    for (int i = 0; i < 4; i++)
        #pragma unroll
        for (int j = 0; j < 4; j++)
            #pragma unroll
            for (int q = 0; q < 4; q++) acc[i][j][q] = 0.0f;

    for (int c = 0; c < NCHUNK; c++) {
        if (c + 2 < NCHUNK) {
            load_chunk_A(sb, (c + 2) % 3, c + 2, i0, tid);
            CP_WAIT(2);
        } else if (c + 1 < NCHUNK) {
            CP_WAIT(1);
        } else {
            CP_WAIT(0);
        }
        __syncthreads();

        uint32_t sA = sb + OFF_A + (c % 3) * A_STAGE;
        uint32_t sB = sb + (c & 1) * 16384;   // B hi chunk reused for lo pass

        #pragma unroll
        for (int ks = 0; ks < 4; ks++) {
            uint32_t colb = ks * 32 + colh2;
            uint32_t aF[4][4], bF[4][2];
            #pragma unroll
            for (int i = 0; i < 4; i++) {
                uint32_t ad = sA + SWZ(aRow + i * 2048 + colb);
                LDSM_X4(aF[i][0], aF[i][1], aF[i][2], aF[i][3], ad);
            }
            #pragma unroll
            for (int jj = 0; jj < 2; jj++) {
                uint32_t r0, r1, r2, r3;
                uint32_t bd = sB + SWZ(bRow + jj * 2048 + colb);
                LDSM_X4(r0, r1, r2, r3, bd);
                bF[2 * jj][0] = r0; bF[2 * jj][1] = r2;
                bF[2 * jj + 1][0] = r1; bF[2 * jj + 1][1] = r3;
            }
            #pragma unroll
            for (int i = 0; i < 4; i++)
                #pragma unroll
                for (int j = 0; j < 4; j++)
                    MMA_BF16(acc[i][j], aF[i], bF[j]);
        }
        __syncthreads();
    }

    // ---------------- fused epilogue ----------------
    const int g = lane >> 2, t = lane & 3;
    const int scol = j0 + nr + t * 2;
    const float NL2E = -1.4426950408889634f;

    float sqc[8], colden[8], colv[8][8];
    #pragma unroll
    for (int j = 0; j < 4; j++) {
        #pragma unroll
        for (int e = 0; e < 2; e++) {
            sqc[j * 2 + e] = g_sq[scol + j * 8 + e];
            colden[j * 2 + e] = 0.0f;
        }
    }

    const int rslot = (bj - bi) * 4 + wn;
    #pragma unroll
    for (int i = 0; i < 4; i++) {
        #pragma unroll
        for (int h = 0; h < 2; h++) {
            const int rg = i0 + mr + i * 16 + h * 8 + g;
            const float sqi = g_sq[rg];
            float v8[8];
            float den = 0.0f;
            #pragma unroll
            for (int j = 0; j < 4; j++) {
                #pragma unroll
                for (int e = 0; e < 2; e++) {
                    const int je = j * 2 + e;
                    float dot = acc[i][j][h * 2 + e];
                    int cg = scol + j * 8 + e;
                    float d2 = fmaxf(fmaf(-2.0f, dot, sqi + sqc[je]), 0.0f);
                    bool self = diag && (cg == rg);
                    // exp(-sqrt(d2)) = 2^( d2*rsqrt(d2) * -log2e )  (2 MUFU + 2 FMA)
                    float ex = ex2_ap(d2 * rsqrt_ap(d2) * NL2E);
                    ex = self ? 0.0f : ex;      // kills the d2==0 NaN
                    den += ex;
                    colden[je] += ex;
                    float v = self ? CUDART_INF_F : d2;
                    v8[je] = v;
                    colv[je][i * 2 + h] = v;
                }
            }
            den += __shfl_xor_sync(0xffffffffu, den, 1);
            den += __shfl_xor_sync(0xffffffffu, den, 2);
            sort8(v8);
            merge8_shfl(v8, 1);
            merge8_shfl(v8, 2);
            if (t == 0) {
                g_pden[(size_t)rg * SLOTS + rslot] = den;
                float4* dst = (float4*)&g_cand[((size_t)rg * SLOTS + rslot) * KNB];
                dst[0] = make_float4(v8[0], v8[1], v8[2], v8[3]);
                dst[1] = make_float4(v8[4], v8[5], v8[6], v8[7]);
            }
        }
    }

    if (!diag) {
        const int cslot = COLBASE + bi * 2 + wm;
        #pragma unroll
        for (int je = 0; je < 8; je++) {
            sort8(colv[je]);
            merge8_shfl(colv[je], 4);
            merge8_shfl(colv[je], 8);
            merge8_shfl(colv[je], 16);
            float cd = colden[je];
            cd += __shfl_xor_sync(0xffffffffu, cd, 4);
            cd += __shfl_xor_sync(0xffffffffu, cd, 8);
            cd += __shfl_xor_sync(0xffffffffu, cd, 16);
            colden[je] = cd;
        }
        if (g == 0) {
            #pragma unroll
            for (int j = 0; j < 4; j++) {
                #pragma unroll
                for (int e = 0; e < 2; e++) {
                    const int je = j * 2 + e;
                    const int cg = scol + j * 8 + e;
                    g_pden[(size_t)cg * SLOTS + cslot] = colden[je];
                    float4* dst = (float4*)&g_cand[((size_t)cg * SLOTS + cslot) * KNB];
                    dst[0] = make_float4(colv[je][0], colv[je][1], colv[je][2], colv[je][3]);
                    dst[1] = make_float4(colv[je][4], colv[je][5], colv[je][6], colv[je][7]);
                }
            }
        }
    }
}

// ---------------------------------------------------------------------------
// merge kernel: one warp per row; reads only the valid slots.
// ---------------------------------------------------------------------------
__global__ __launch_bounds__(256) void merge_kernel(int n) {
    const int row = (blockIdx.x * 256 + threadIdx.x) >> 5;
    const int lane = threadIdx.x & 31;
    if (row >= n) return;
    const int bi = row >> 7;
    const int nrow = (NB - bi) * 4;
    const int ntot = nrow + 2 * bi;

    float l8[8];
    #pragma unroll
    for (int q = 0; q < 8; q++) l8[q] = CUDART_INF_F;
    float den = 0.0f;

    for (int s = lane; s < ntot; s += 32) {
        int slot = (s < nrow) ? s : (COLBASE + (s - nrow));
        const float4* src = (const float4*)&g_cand[((size_t)row * SLOTS + slot) * KNB];
        float o[8];
        float4 a = src[0], b = src[1];
        o[0] = a.x; o[1] = a.y; o[2] = a.z; o[3] = a.w;
        o[4] = b.x; o[5] = b.y; o[6] = b.z; o[7] = b.w;
        merge8(l8, o);
        den += g_pden[(size_t)row * SLOTS + slot];
    }
    merge8_shfl(l8, 1);
    merge8_shfl(l8, 2);
    merge8_shfl(l8, 4);
    merge8_shfl(l8, 8);
    merge8_shfl(l8, 16);
    #pragma unroll
    for (int m = 1; m < 32; m <<= 1) den += __shfl_xor_sync(0xffffffffu, den, m);

    if (lane == 0) {
        float ds = 0.0f;
        #pragma unroll
        for (int q = 0; q < KNB; q++) ds += sqrtf(fmaxf(l8[q], 0.0f));
        g_loss[row] = ds * (1.0f / KNB) + logf(den);
    }
}

// ---------------------------------------------------------------------------
__global__ void final_kernel(float* __restrict__ out, int n) {
    __shared__ float sv[256];
    const int tid = threadIdx.x;
    float s = 0.0f;
    for (int i = tid; i < n; i += 256) s += g_loss[i];
    sv[tid] = s;
    __syncthreads();
    for (int o = 128; o; o >>= 1) {
        if (tid < o) sv[tid] += sv[tid + o];
        __syncthreads();
    }
    if (tid == 0) out[0] = sv[0] / (float)n;
}

// ---------------------------------------------------------------------------
extern "C" void kernel_launch(void* const* d_in, const int* in_sizes, int n_in,
                              void* d_out, int out_size) {
    const float* x = (const float*)d_in[0];
    float* out = (float*)d_out;
    const int n = in_sizes[0] / DIM;   // 8192
    const int tri = NB * (NB + 1) / 2; // 2080

    cudaFuncSetAttribute(fused_gemm, cudaFuncAttributeMaxDynamicSharedMemorySize,
                         SMEM_TOTAL);

    pack_kernel<<<(n * DIM) / 256, 256>>>(x);
    sqnorm_kernel<<<(n + 7) / 8, 256>>>(x, n);
    fused_gemm<<<tri, 256, SMEM_TOTAL>>>(n);
    merge_kernel<<<(n * 32) / 256, 256>>>(n);
    final_kernel<<<1, 256>>>(out, n);
}

// round 9
// speedup vs baseline: 5.5280x; 1.3701x over previous
#include <cuda_runtime.h>
#include <cuda_bf16.h>
#include <math.h>
#include <math_constants.h>
#include <cstdint>

#define NPTS 8192
#define DIM  128
#define KNB  8
#define NB   64            // 8192/128 blocks per side
#define NCHUNK 4           // 4 x 64-k chunks (A: [hi|lo] K=256; B hi reused twice)
#define SLOTS 384          // per row: 256 row-side + 128 col-side
#define COLBASE 256

// ------------------------- device scratch (no allocs) -----------------------
__device__ float g_sq[NPTS];
__device__ float g_loss[NPTS];
__device__ float g_pden[(size_t)NPTS * SLOTS];
__device__ float g_cand[(size_t)NPTS * SLOTS * KNB];
__device__ uint4 g_pa[(size_t)NPTS * 32];   // 256 bf16 per row  [hi|lo]
__device__ uint4 g_pb[(size_t)NPTS * 16];   // 128 bf16 per row  [hi]

// ------------------------- helpers ------------------------------------------
__device__ __forceinline__ uint32_t smem_u32(const void* p) {
    uint32_t a;
    asm("{ .reg .u64 t; cvta.to.shared.u64 t, %1; cvt.u32.u64 %0, t; }"
        : "=r"(a) : "l"(p));
    return a;
}
#define SWZ(o) ((o) ^ (((o) >> 3) & 0x70))

#define CP_ASYNC16(dst, src) \
    asm volatile("cp.async.cg.shared.global [%0], [%1], 16;" \
                 :: "r"(dst), "l"(src) : "memory")
#define CP_COMMIT() asm volatile("cp.async.commit_group;" ::: "memory")
#define CP_WAIT(N)  asm volatile("cp.async.wait_group %0;" :: "n"(N) : "memory")

#define LDSM_X4(r0, r1, r2, r3, a) \
    asm volatile("ldmatrix.sync.aligned.m8n8.x4.shared.b16 {%0,%1,%2,%3}, [%4];" \
                 : "=r"(r0), "=r"(r1), "=r"(r2), "=r"(r3) : "r"(a))

#define MMA_BF16(c, a, b) \
    asm volatile("mma.sync.aligned.m16n8k16.row.col.f32.bf16.bf16.f32 " \
                 "{%0,%1,%2,%3}, {%4,%5,%6,%7}, {%8,%9}, {%0,%1,%2,%3};" \
                 : "+f"((c)[0]), "+f"((c)[1]), "+f"((c)[2]), "+f"((c)[3]) \
                 : "r"((a)[0]), "r"((a)[1]), "r"((a)[2]), "r"((a)[3]), \
                   "r"((b)[0]), "r"((b)[1]))

// SMEM: B resident 32KB at 0; A 3 stages x 16KB at 32KB. Total 80KB.
// 2 CTAs/SM -> 160KB of 227KB.
#define OFF_A    32768
#define A_STAGE  16384
#define SMEM_TOTAL (32768 + 3 * 16384)

// ---- MUFU transcendentals ---------------------------------------------------
__device__ __forceinline__ float rsqrt_ap(float x) {
    float y; asm("rsqrt.approx.f32 %0, %1;" : "=f"(y) : "f"(x)); return y;
}
__device__ __forceinline__ float ex2_ap(float x) {
    float y; asm("ex2.approx.f32 %0, %1;" : "=f"(y) : "f"(x)); return y;
}

// ---- sorting networks -------------------------------------------------------
__device__ __forceinline__ void cas(float& a, float& b) {
    float lo = fminf(a, b), hi = fmaxf(a, b); a = lo; b = hi;
}
__device__ __forceinline__ void sort8(float* v) {
    cas(v[0],v[1]); cas(v[2],v[3]); cas(v[4],v[5]); cas(v[6],v[7]);
    cas(v[0],v[2]); cas(v[1],v[3]); cas(v[4],v[6]); cas(v[5],v[7]);
    cas(v[1],v[2]); cas(v[5],v[6]);
    cas(v[0],v[4]); cas(v[1],v[5]); cas(v[2],v[6]); cas(v[3],v[7]);
    cas(v[2],v[4]); cas(v[3],v[5]);
    cas(v[1],v[2]); cas(v[3],v[4]); cas(v[5],v[6]);
}
__device__ __forceinline__ void bitonic8(float* v) {
    cas(v[0],v[4]); cas(v[1],v[5]); cas(v[2],v[6]); cas(v[3],v[7]);
    cas(v[0],v[2]); cas(v[1],v[3]); cas(v[4],v[6]); cas(v[5],v[7]);
    cas(v[0],v[1]); cas(v[2],v[3]); cas(v[4],v[5]); cas(v[6],v[7]);
}
__device__ __forceinline__ void merge8(float* t, const float* o) {
    float m[8];
    #pragma unroll
    for (int q = 0; q < 8; q++) m[q] = fminf(t[q], o[7 - q]);
    bitonic8(m);
    #pragma unroll
    for (int q = 0; q < 8; q++) t[q] = m[q];
}
__device__ __forceinline__ void merge8_shfl(float* t, int mask) {
    float o[8];
    #pragma unroll
    for (int q = 0; q < 8; q++) o[q] = __shfl_xor_sync(0xffffffffu, t[7 - q], mask);
    #pragma unroll
    for (int q = 0; q < 8; q++) t[q] = fminf(t[q], o[q]);
    bitonic8(t);
}

// ---------------------------------------------------------------------------
__global__ void pack_kernel(const float* __restrict__ x) {
    int t = blockIdx.x * blockDim.x + threadIdx.x;
    int i = t >> 7, col = t & 127;
    float v = x[(size_t)i * DIM + col];
    __nv_bfloat16 hi = __float2bfloat16(v);
    __nv_bfloat16 lo = __float2bfloat16(v - __bfloat162float(hi));
    __nv_bfloat16* pa = (__nv_bfloat16*)g_pa;
    __nv_bfloat16* pb = (__nv_bfloat16*)g_pb;
    pa[(size_t)i * 256 + col] = hi;
    pa[(size_t)i * 256 + 128 + col] = lo;
    pb[(size_t)i * 128 + col] = hi;
}

__global__ void sqnorm_kernel(const float* __restrict__ x, int n) {
    int warp = (blockIdx.x * blockDim.x + threadIdx.x) >> 5;
    int lane = threadIdx.x & 31;
    if (warp >= n) return;
    float4 v = ((const float4*)(x + (size_t)warp * DIM))[lane];
    float s = v.x * v.x + v.y * v.y + v.z * v.z + v.w * v.w;
    #pragma unroll
    for (int o = 16; o; o >>= 1) s += __shfl_xor_sync(0xffffffffu, s, o);
    if (lane == 0) g_sq[warp] = s;
}

// ---------------------------------------------------------------------------
// Symmetric fused GEMM: 128x128 tiles over upper triangle, warps 2(m)x4(n)
// of 64x32. B (hi only) SMEM-resident; A 3-stage pipelined. 2 CTAs/SM.
// ---------------------------------------------------------------------------
__device__ __forceinline__ void load_chunk_A(uint32_t sb, int stage, int c,
                                             int i0, int tid) {
    uint32_t s = sb + OFF_A + stage * A_STAGE;
    #pragma unroll
    for (int r = 0; r < 4; r++) {                 // 1024 uint4
        int idx = tid + r * 256;
        int row = idx >> 3, q = idx & 7;
        const uint4* src = &g_pa[(size_t)(i0 + row) * 32 + c * 8 + q];
        CP_ASYNC16(s + SWZ(row * 128 + q * 16), src);
    }
    CP_COMMIT();
}

__global__ __launch_bounds__(256, 2) void fused_gemm(int n) {
    extern __shared__ __align__(16) char smem[];
    const uint32_t sb = smem_u32(smem);
    const int tid = threadIdx.x;
    const int wid = tid >> 5;
    const int lane = tid & 31;
    const int wm = wid & 1;          // 64-row half
    const int wn = wid >> 1;         // 32-col strip
    const int mr = wm * 64;
    const int nr = wn * 32;

    int rem = blockIdx.x, bi = 0;
    while (rem >= NB - bi) { rem -= NB - bi; bi++; }
    const int bj = bi + rem;
    const int i0 = bi * 128, j0 = bj * 128;
    const bool diag = (bi == bj);

    // prologue: B resident (2 x 64-k chunks = 2048 uint4), then A0, A1
    #pragma unroll
    for (int r = 0; r < 8; r++) {
        int idx = tid + r * 256;
        int kc = idx >> 10, w = idx & 1023;
        int row = w >> 3, q = w & 7;
        const uint4* src = &g_pb[(size_t)(j0 + row) * 16 + kc * 8 + q];
        CP_ASYNC16(sb + kc * 16384 + SWZ(row * 128 + q * 16), src);
    }
    CP_COMMIT();
    load_chunk_A(sb, 0, 0, i0, tid);
    load_chunk_A(sb, 1, 1, i0, tid);

    const int row_off = lane & 15;
    const int colh2 = (lane >> 4) * 16;
    const uint32_t aRow = (uint32_t)(mr + row_off) * 128;
    const uint32_t bRow = (uint32_t)(nr + row_off) * 128;

    float acc[4][4][4];
    #pragma unroll
    for (int i = 0; i < 4; i++)
        #pragma unroll
        for (int j = 0; j < 4; j++)
            #pragma unroll
            for (int q = 0; q < 4; q++) acc[i][j][q] = 0.0f;

    for (int c = 0; c < NCHUNK; c++) {
        if (c + 2 < NCHUNK) {
            load_chunk_A(sb, (c + 2) % 3, c + 2, i0, tid);
            CP_WAIT(2);
        } else if (c + 1 < NCHUNK) {
            CP_WAIT(1);
        } else {
            CP_WAIT(0);
        }
        __syncthreads();

        uint32_t sA = sb + OFF_A + (c % 3) * A_STAGE;
        uint32_t sB = sb + (c & 1) * 16384;   // B hi chunk reused for lo pass

        #pragma unroll
        for (int ks = 0; ks < 4; ks++) {
            uint32_t colb = ks * 32 + colh2;
            uint32_t aF[4][4], bF[4][2];
            #pragma unroll
            for (int i = 0; i < 4; i++) {
                uint32_t ad = sA + SWZ(aRow + i * 2048 + colb);
                LDSM_X4(aF[i][0], aF[i][1], aF[i][2], aF[i][3], ad);
            }
            #pragma unroll
            for (int jj = 0; jj < 2; jj++) {
                uint32_t r0, r1, r2, r3;
                uint32_t bd = sB + SWZ(bRow + jj * 2048 + colb);
                LDSM_X4(r0, r1, r2, r3, bd);
                bF[2 * jj][0] = r0; bF[2 * jj][1] = r2;
                bF[2 * jj + 1][0] = r1; bF[2 * jj + 1][1] = r3;
            }
            #pragma unroll
            for (int i = 0; i < 4; i++)
                #pragma unroll
                for (int j = 0; j < 4; j++)
                    MMA_BF16(acc[i][j], aF[i], bF[j]);
        }
        __syncthreads();
    }

    // ---------------- fused epilogue (no colv: col pass reads acc) ----------
    const int g = lane >> 2, t = lane & 3;
    const int scol = j0 + nr + t * 2;
    const float NL2E = -1.4426950408889634f;

    float sqc[8], sqr[8], colden[8];
    #pragma unroll
    for (int j = 0; j < 4; j++) {
        #pragma unroll
        for (int e = 0; e < 2; e++) {
            sqc[j * 2 + e] = g_sq[scol + j * 8 + e];
            colden[j * 2 + e] = 0.0f;
        }
    }
    #pragma unroll
    for (int i = 0; i < 4; i++)
        #pragma unroll
        for (int h = 0; h < 2; h++)
            sqr[i * 2 + h] = g_sq[i0 + mr + i * 16 + h * 8 + g];

    const int rslot = (bj - bi) * 4 + wn;
    #pragma unroll
    for (int i = 0; i < 4; i++) {
        #pragma unroll
        for (int h = 0; h < 2; h++) {
            const int rg = i0 + mr + i * 16 + h * 8 + g;
            const float sqi = sqr[i * 2 + h];
            float v8[8];
            float den = 0.0f;
            #pragma unroll
            for (int j = 0; j < 4; j++) {
                #pragma unroll
                for (int e = 0; e < 2; e++) {
                    const int je = j * 2 + e;
                    float dot = acc[i][j][h * 2 + e];
                    int cg = scol + j * 8 + e;
                    float d2 = fmaxf(fmaf(-2.0f, dot, sqi + sqc[je]), 0.0f);
                    bool self = diag && (cg == rg);
                    float ex = ex2_ap(d2 * rsqrt_ap(d2) * NL2E);
                    ex = self ? 0.0f : ex;      // kills the d2==0 NaN
                    den += ex;
                    colden[je] += ex;
                    v8[je] = self ? CUDART_INF_F : d2;
                }
            }
            den += __shfl_xor_sync(0xffffffffu, den, 1);
            den += __shfl_xor_sync(0xffffffffu, den, 2);
            sort8(v8);
            merge8_shfl(v8, 1);
            merge8_shfl(v8, 2);
            if (t == 0) {
                g_pden[(size_t)rg * SLOTS + rslot] = den;
                float4* dst = (float4*)&g_cand[((size_t)rg * SLOTS + rslot) * KNB];
                dst[0] = make_float4(v8[0], v8[1], v8[2], v8[3]);
                dst[1] = make_float4(v8[4], v8[5], v8[6], v8[7]);
            }
        }
    }

    if (!diag) {
        const int cslot = COLBASE + bi * 2 + wm;
        #pragma unroll
        for (int j = 0; j < 4; j++) {
            #pragma unroll
            for (int e = 0; e < 2; e++) {
                const int je = j * 2 + e;
                const int cg = scol + j * 8 + e;
                float c8[8];
                #pragma unroll
                for (int i = 0; i < 4; i++) {
                    #pragma unroll
                    for (int h = 0; h < 2; h++) {
                        float dot = acc[i][j][h * 2 + e];
                        float d2 = fmaxf(fmaf(-2.0f, dot, sqr[i * 2 + h] + sqc[je]), 0.0f);
                        c8[i * 2 + h] = d2;   // diag tiles never reach here -> no self
                    }
                }
                sort8(c8);
                merge8_shfl(c8, 4);
                merge8_shfl(c8, 8);
                merge8_shfl(c8, 16);
                float cd = colden[je];
                cd += __shfl_xor_sync(0xffffffffu, cd, 4);
                cd += __shfl_xor_sync(0xffffffffu, cd, 8);
                cd += __shfl_xor_sync(0xffffffffu, cd, 16);
                if (g == 0) {
                    g_pden[(size_t)cg * SLOTS + cslot] = cd;
                    float4* dst = (float4*)&g_cand[((size_t)cg * SLOTS + cslot) * KNB];
                    dst[0] = make_float4(c8[0], c8[1], c8[2], c8[3]);
                    dst[1] = make_float4(c8[4], c8[5], c8[6], c8[7]);
                }
            }
        }
    }
}

// ---------------------------------------------------------------------------
// merge kernel: one warp per row; reads only the valid slots.
// ---------------------------------------------------------------------------
__global__ __launch_bounds__(256) void merge_kernel(int n) {
    const int row = (blockIdx.x * 256 + threadIdx.x) >> 5;
    const int lane = threadIdx.x & 31;
    if (row >= n) return;
    const int bi = row >> 7;
    const int nrow = (NB - bi) * 4;
    const int ntot = nrow + 2 * bi;

    float l8[8];
    #pragma unroll
    for (int q = 0; q < 8; q++) l8[q] = CUDART_INF_F;
    float den = 0.0f;

    for (int s = lane; s < ntot; s += 32) {
        int slot = (s < nrow) ? s : (COLBASE + (s - nrow));
        const float4* src = (const float4*)&g_cand[((size_t)row * SLOTS + slot) * KNB];
        float o[8];
        float4 a = src[0], b = src[1];
        o[0] = a.x; o[1] = a.y; o[2] = a.z; o[3] = a.w;
        o[4] = b.x; o[5] = b.y; o[6] = b.z; o[7] = b.w;
        merge8(l8, o);
        den += g_pden[(size_t)row * SLOTS + slot];
    }
    merge8_shfl(l8, 1);
    merge8_shfl(l8, 2);
    merge8_shfl(l8, 4);
    merge8_shfl(l8, 8);
    merge8_shfl(l8, 16);
    #pragma unroll
    for (int m = 1; m < 32; m <<= 1) den += __shfl_xor_sync(0xffffffffu, den, m);

    if (lane == 0) {
        float ds = 0.0f;
        #pragma unroll
        for (int q = 0; q < KNB; q++) ds += sqrtf(fmaxf(l8[q], 0.0f));
        g_loss[row] = ds * (1.0f / KNB) + logf(den);
    }
}

// ---------------------------------------------------------------------------
__global__ void final_kernel(float* __restrict__ out, int n) {
    __shared__ float sv[256];
    const int tid = threadIdx.x;
    float s = 0.0f;
    for (int i = tid; i < n; i += 256) s += g_loss[i];
    sv[tid] = s;
    __syncthreads();
    for (int o = 128; o; o >>= 1) {
        if (tid < o) sv[tid] += sv[tid + o];
        __syncthreads();
    }
    if (tid == 0) out[0] = sv[0] / (float)n;
}

// ---------------------------------------------------------------------------
extern "C" void kernel_launch(void* const* d_in, const int* in_sizes, int n_in,
                              void* d_out, int out_size) {
    const float* x = (const float*)d_in[0];
    float* out = (float*)d_out;
    const int n = in_sizes[0] / DIM;   // 8192
    const int tri = NB * (NB + 1) / 2; // 2080

    cudaFuncSetAttribute(fused_gemm, cudaFuncAttributeMaxDynamicSharedMemorySize,
                         SMEM_TOTAL);

    pack_kernel<<<(n * DIM) / 256, 256>>>(x);
    sqnorm_kernel<<<(n + 7) / 8, 256>>>(x, n);
    fused_gemm<<<tri, 256, SMEM_TOTAL>>>(n);
    merge_kernel<<<(n * 32) / 256, 256>>>(n);
    final_kernel<<<1, 256>>>(out, n);
}

// round 10
// speedup vs baseline: 5.7339x; 1.0372x over previous
#include <cuda_runtime.h>
#include <cuda_bf16.h>
#include <math.h>
#include <math_constants.h>
#include <cstdint>

#define NPTS 8192
#define DIM  128
#define KNB  8
#define NB   64            // 8192/128 blocks per side
#define NCHUNK 4           // 4 x 64-k chunks (A: [hi|lo] K=256; B hi reused twice)
#define SLOTS 384          // per row: 256 row-side + 128 col-side
#define COLBASE 256

// ------------------------- device scratch (no allocs) -----------------------
__device__ float g_sq[NPTS];
__device__ float g_loss[NPTS];
__device__ float g_pden[(size_t)NPTS * SLOTS];
__device__ float g_cand[(size_t)NPTS * SLOTS * KNB];
__device__ uint4 g_pa[(size_t)NPTS * 32];   // 256 bf16 per row  [hi|lo]
__device__ uint4 g_pb[(size_t)NPTS * 16];   // 128 bf16 per row  [hi]

// ------------------------- helpers ------------------------------------------
__device__ __forceinline__ uint32_t smem_u32(const void* p) {
    uint32_t a;
    asm("{ .reg .u64 t; cvta.to.shared.u64 t, %1; cvt.u32.u64 %0, t; }"
        : "=r"(a) : "l"(p));
    return a;
}
#define SWZ(o) ((o) ^ (((o) >> 3) & 0x70))

#define CP_ASYNC16(dst, src) \
    asm volatile("cp.async.cg.shared.global [%0], [%1], 16;" \
                 :: "r"(dst), "l"(src) : "memory")
#define CP_COMMIT() asm volatile("cp.async.commit_group;" ::: "memory")
#define CP_WAIT(N)  asm volatile("cp.async.wait_group %0;" :: "n"(N) : "memory")

#define LDSM_X4(r0, r1, r2, r3, a) \
    asm volatile("ldmatrix.sync.aligned.m8n8.x4.shared.b16 {%0,%1,%2,%3}, [%4];" \
                 : "=r"(r0), "=r"(r1), "=r"(r2), "=r"(r3) : "r"(a))

#define MMA_BF16(c, a, b) \
    asm volatile("mma.sync.aligned.m16n8k16.row.col.f32.bf16.bf16.f32 " \
                 "{%0,%1,%2,%3}, {%4,%5,%6,%7}, {%8,%9}, {%0,%1,%2,%3};" \
                 : "+f"((c)[0]), "+f"((c)[1]), "+f"((c)[2]), "+f"((c)[3]) \
                 : "r"((a)[0]), "r"((a)[1]), "r"((a)[2]), "r"((a)[3]), \
                   "r"((b)[0]), "r"((b)[1]))

// SMEM: B resident 32KB at 0; A 4 stages x 16KB at 32KB. Total 96KB.
// 2 CTAs/SM -> 192KB of 227KB.
#define OFF_A    32768
#define A_STAGE  16384
#define SMEM_TOTAL (32768 + 4 * 16384)

// ---- MUFU transcendentals ---------------------------------------------------
__device__ __forceinline__ float rsqrt_ap(float x) {
    float y; asm("rsqrt.approx.f32 %0, %1;" : "=f"(y) : "f"(x)); return y;
}
__device__ __forceinline__ float ex2_ap(float x) {
    float y; asm("ex2.approx.f32 %0, %1;" : "=f"(y) : "f"(x)); return y;
}

// ---- sorting networks -------------------------------------------------------
__device__ __forceinline__ void cas(float& a, float& b) {
    float lo = fminf(a, b), hi = fmaxf(a, b); a = lo; b = hi;
}
__device__ __forceinline__ void sort8(float* v) {
    cas(v[0],v[1]); cas(v[2],v[3]); cas(v[4],v[5]); cas(v[6],v[7]);
    cas(v[0],v[2]); cas(v[1],v[3]); cas(v[4],v[6]); cas(v[5],v[7]);
    cas(v[1],v[2]); cas(v[5],v[6]);
    cas(v[0],v[4]); cas(v[1],v[5]); cas(v[2],v[6]); cas(v[3],v[7]);
    cas(v[2],v[4]); cas(v[3],v[5]);
    cas(v[1],v[2]); cas(v[3],v[4]); cas(v[5],v[6]);
}
__device__ __forceinline__ void bitonic8(float* v) {
    cas(v[0],v[4]); cas(v[1],v[5]); cas(v[2],v[6]); cas(v[3],v[7]);
    cas(v[0],v[2]); cas(v[1],v[3]); cas(v[4],v[6]); cas(v[5],v[7]);
    cas(v[0],v[1]); cas(v[2],v[3]); cas(v[4],v[5]); cas(v[6],v[7]);
}
__device__ __forceinline__ void merge8(float* t, const float* o) {
    float m[8];
    #pragma unroll
    for (int q = 0; q < 8; q++) m[q] = fminf(t[q], o[7 - q]);
    bitonic8(m);
    #pragma unroll
    for (int q = 0; q < 8; q++) t[q] = m[q];
}
__device__ __forceinline__ void merge8_shfl(float* t, int mask) {
    float o[8];
    #pragma unroll
    for (int q = 0; q < 8; q++) o[q] = __shfl_xor_sync(0xffffffffu, t[7 - q], mask);
    #pragma unroll
    for (int q = 0; q < 8; q++) t[q] = fminf(t[q], o[q]);
    bitonic8(t);
}

// ---------------------------------------------------------------------------
// fused pack + sqnorm: one warp per row
// ---------------------------------------------------------------------------
__global__ void pack_kernel(const float* __restrict__ x, int n) {
    int warp = (blockIdx.x * blockDim.x + threadIdx.x) >> 5;
    int lane = threadIdx.x & 31;
    if (warp >= n) return;
    float4 v = ((const float4*)(x + (size_t)warp * DIM))[lane];

    float s = v.x * v.x + v.y * v.y + v.z * v.z + v.w * v.w;
    #pragma unroll
    for (int o = 16; o; o >>= 1) s += __shfl_xor_sync(0xffffffffu, s, o);
    if (lane == 0) g_sq[warp] = s;

    __nv_bfloat16 hx = __float2bfloat16(v.x), hy = __float2bfloat16(v.y);
    __nv_bfloat16 hz = __float2bfloat16(v.z), hw = __float2bfloat16(v.w);
    __nv_bfloat16 lx = __float2bfloat16(v.x - __bfloat162float(hx));
    __nv_bfloat16 ly = __float2bfloat16(v.y - __bfloat162float(hy));
    __nv_bfloat16 lz = __float2bfloat16(v.z - __bfloat162float(hz));
    __nv_bfloat16 lw = __float2bfloat16(v.w - __bfloat162float(hw));

    __nv_bfloat162* pa2 = (__nv_bfloat162*)g_pa;   // 128 pairs per row
    __nv_bfloat162* pb2 = (__nv_bfloat162*)g_pb;   // 64 pairs per row
    size_t ra = (size_t)warp * 128;
    pa2[ra + lane * 2]          = __nv_bfloat162(hx, hy);
    pa2[ra + lane * 2 + 1]      = __nv_bfloat162(hz, hw);
    pa2[ra + 64 + lane * 2]     = __nv_bfloat162(lx, ly);
    pa2[ra + 64 + lane * 2 + 1] = __nv_bfloat162(lz, lw);
    size_t rb = (size_t)warp * 64;
    pb2[rb + lane * 2]     = __nv_bfloat162(hx, hy);
    pb2[rb + lane * 2 + 1] = __nv_bfloat162(hz, hw);
}

// ---------------------------------------------------------------------------
// Symmetric fused GEMM: 128x128 tiles over upper triangle, warps 2(m)x4(n)
// of 64x32. B (hi only) SMEM-resident; A 4-stage (no reuse -> no tail sync).
// 2 CTAs/SM.
// ---------------------------------------------------------------------------
__device__ __forceinline__ void load_chunk_A(uint32_t sb, int stage, int c,
                                             int i0, int tid) {
    uint32_t s = sb + OFF_A + stage * A_STAGE;
    #pragma unroll
    for (int r = 0; r < 4; r++) {                 // 1024 uint4
        int idx = tid + r * 256;
        int row = idx >> 3, q = idx & 7;
        const uint4* src = &g_pa[(size_t)(i0 + row) * 32 + c * 8 + q];
        CP_ASYNC16(s + SWZ(row * 128 + q * 16), src);
    }
    CP_COMMIT();
}

__global__ __launch_bounds__(256, 2) void fused_gemm(int n) {
    extern __shared__ __align__(16) char smem[];
    const uint32_t sb = smem_u32(smem);
    const int tid = threadIdx.x;
    const int wid = tid >> 5;
    const int lane = tid & 31;
    const int wm = wid & 1;          // 64-row half
    const int wn = wid >> 1;         // 32-col strip
    const int mr = wm * 64;
    const int nr = wn * 32;

    int rem = blockIdx.x, bi = 0;
    while (rem >= NB - bi) { rem -= NB - bi; bi++; }
    const int bj = bi + rem;
    const int i0 = bi * 128, j0 = bj * 128;
    const bool diag = (bi == bj);

    // prologue: B resident (2 x 64-k chunks = 2048 uint4), then A0, A1, A2
    #pragma unroll
    for (int r = 0; r < 8; r++) {
        int idx = tid + r * 256;
        int kc = idx >> 10, w = idx & 1023;
        int row = w >> 3, q = w & 7;
        const uint4* src = &g_pb[(size_t)(j0 + row) * 16 + kc * 8 + q];
        CP_ASYNC16(sb + kc * 16384 + SWZ(row * 128 + q * 16), src);
    }
    CP_COMMIT();
    load_chunk_A(sb, 0, 0, i0, tid);
    load_chunk_A(sb, 1, 1, i0, tid);
    load_chunk_A(sb, 2, 2, i0, tid);

    const int row_off = lane & 15;
    const int colh2 = (lane >> 4) * 16;
    const uint32_t aRow = (uint32_t)(mr + row_off) * 128;
    const uint32_t bRow = (uint32_t)(nr + row_off) * 128;

    float acc[4][4][4];
    #pragma unroll
    for (int i = 0; i < 4; i++)
        #pragma unroll
        for (int j = 0; j < 4; j++)
            #pragma unroll
            for (int q = 0; q < 4; q++) acc[i][j][q] = 0.0f;

    #pragma unroll
    for (int c = 0; c < NCHUNK; c++) {
        if (c == 0) { load_chunk_A(sb, 3, 3, i0, tid); CP_WAIT(3); }
        else if (c == 1) { CP_WAIT(2); }
        else if (c == 2) { CP_WAIT(1); }
        else { CP_WAIT(0); }
        __syncthreads();    // all warps' chunk c visible; stages never reused

        uint32_t sA = sb + OFF_A + c * A_STAGE;
        uint32_t sB = sb + (c & 1) * 16384;   // B hi chunk reused for lo pass

        #pragma unroll
        for (int ks = 0; ks < 4; ks++) {
            uint32_t colb = ks * 32 + colh2;
            uint32_t aF[4][4], bF[4][2];
            #pragma unroll
            for (int i = 0; i < 4; i++) {
                uint32_t ad = sA + SWZ(aRow + i * 2048 + colb);
                LDSM_X4(aF[i][0], aF[i][1], aF[i][2], aF[i][3], ad);
            }
            #pragma unroll
            for (int jj = 0; jj < 2; jj++) {
                uint32_t r0, r1, r2, r3;
                uint32_t bd = sB + SWZ(bRow + jj * 2048 + colb);
                LDSM_X4(r0, r1, r2, r3, bd);
                bF[2 * jj][0] = r0; bF[2 * jj][1] = r2;
                bF[2 * jj + 1][0] = r1; bF[2 * jj + 1][1] = r3;
            }
            #pragma unroll
            for (int i = 0; i < 4; i++)
                #pragma unroll
                for (int j = 0; j < 4; j++)
                    MMA_BF16(acc[i][j], aF[i], bF[j]);
        }
    }

    // ---------------- fused epilogue ----------------
    const int g = lane >> 2, t = lane & 3;
    const int scol = j0 + nr + t * 2;
    const float NL2E = -1.4426950408889634f;

    float sqc[8], sqr[8], colden[8];
    #pragma unroll
    for (int j = 0; j < 4; j++) {
        #pragma unroll
        for (int e = 0; e < 2; e++) {
            sqc[j * 2 + e] = g_sq[scol + j * 8 + e];
            colden[j * 2 + e] = 0.0f;
        }
    }
    #pragma unroll
    for (int i = 0; i < 4; i++)
        #pragma unroll
        for (int h = 0; h < 2; h++)
            sqr[i * 2 + h] = g_sq[i0 + mr + i * 16 + h * 8 + g];

    const int rslot = (bj - bi) * 4 + wn;
    #pragma unroll
    for (int i = 0; i < 4; i++) {
        #pragma unroll
        for (int h = 0; h < 2; h++) {
            const int rg = i0 + mr + i * 16 + h * 8 + g;
            const float sqi = sqr[i * 2 + h];
            float v8[8];
            float den = 0.0f;
            #pragma unroll
            for (int j = 0; j < 4; j++) {
                #pragma unroll
                for (int e = 0; e < 2; e++) {
                    const int je = j * 2 + e;
                    float dot = acc[i][j][h * 2 + e];
                    int cg = scol + j * 8 + e;
                    float d2 = fmaxf(fmaf(-2.0f, dot, sqi + sqc[je]), 0.0f);
                    bool self = diag && (cg == rg);
                    float ex = ex2_ap(d2 * rsqrt_ap(d2) * NL2E);
                    ex = self ? 0.0f : ex;      // kills the d2==0 NaN
                    den += ex;
                    colden[je] += ex;
                    v8[je] = self ? CUDART_INF_F : d2;
                }
            }
            den += __shfl_xor_sync(0xffffffffu, den, 1);
            den += __shfl_xor_sync(0xffffffffu, den, 2);
            sort8(v8);
            merge8_shfl(v8, 1);
            merge8_shfl(v8, 2);
            if (t == 0) {
                g_pden[(size_t)rg * SLOTS + rslot] = den;
                float4* dst = (float4*)&g_cand[((size_t)rg * SLOTS + rslot) * KNB];
                dst[0] = make_float4(v8[0], v8[1], v8[2], v8[3]);
                dst[1] = make_float4(v8[4], v8[5], v8[6], v8[7]);
            }
        }
    }

    if (!diag) {
        const int cslot = COLBASE + bi * 2 + wm;
        #pragma unroll
        for (int j = 0; j < 4; j++) {
            #pragma unroll
            for (int e = 0; e < 2; e++) {
                const int je = j * 2 + e;
                const int cg = scol + j * 8 + e;
                float c8[8];
                #pragma unroll
                for (int i = 0; i < 4; i++) {
                    #pragma unroll
                    for (int h = 0; h < 2; h++) {
                        float dot = acc[i][j][h * 2 + e];
                        float d2 = fmaxf(fmaf(-2.0f, dot, sqr[i * 2 + h] + sqc[je]), 0.0f);
                        c8[i * 2 + h] = d2;   // off-diag only -> no self here
                    }
                }
                sort8(c8);
                merge8_shfl(c8, 4);
                merge8_shfl(c8, 8);
                merge8_shfl(c8, 16);
                float cd = colden[je];
                cd += __shfl_xor_sync(0xffffffffu, cd, 4);
                cd += __shfl_xor_sync(0xffffffffu, cd, 8);
                cd += __shfl_xor_sync(0xffffffffu, cd, 16);
                if (g == 0) {
                    g_pden[(size_t)cg * SLOTS + cslot] = cd;
                    float4* dst = (float4*)&g_cand[((size_t)cg * SLOTS + cslot) * KNB];
                    dst[0] = make_float4(c8[0], c8[1], c8[2], c8[3]);
                    dst[1] = make_float4(c8[4], c8[5], c8[6], c8[7]);
                }
            }
        }
    }
}

// ---------------------------------------------------------------------------
// merge kernel: one warp per row; software-pipelined slot loads (MLP=2).
// ---------------------------------------------------------------------------
__global__ __launch_bounds__(256) void merge_kernel(int n) {
    const int row = (blockIdx.x * 256 + threadIdx.x) >> 5;
    const int lane = threadIdx.x & 31;
    if (row >= n) return;
    const int bi = row >> 7;
    const int nrow = (NB - bi) * 4;
    const int ntot = nrow + 2 * bi;

    float l8[8];
    #pragma unroll
    for (int q = 0; q < 8; q++) l8[q] = CUDART_INF_F;
    float den = 0.0f;

    int s = lane;
    float4 a, b; float pd = 0.0f;
    if (s < ntot) {
        int slot = (s < nrow) ? s : (COLBASE + (s - nrow));
        const float4* src = (const float4*)&g_cand[((size_t)row * SLOTS + slot) * KNB];
        a = src[0]; b = src[1];
        pd = g_pden[(size_t)row * SLOTS + slot];
    }
    while (s < ntot) {
        int s2 = s + 32;
        float4 a2, b2; float pd2 = 0.0f;
        if (s2 < ntot) {
            int slot2 = (s2 < nrow) ? s2 : (COLBASE + (s2 - nrow));
            const float4* src2 = (const float4*)&g_cand[((size_t)row * SLOTS + slot2) * KNB];
            a2 = src2[0]; b2 = src2[1];
            pd2 = g_pden[(size_t)row * SLOTS + slot2];
        }
        float o[8];
        o[0] = a.x; o[1] = a.y; o[2] = a.z; o[3] = a.w;
        o[4] = b.x; o[5] = b.y; o[6] = b.z; o[7] = b.w;
        merge8(l8, o);
        den += pd;
        a = a2; b = b2; pd = pd2; s = s2;
    }
    merge8_shfl(l8, 1);
    merge8_shfl(l8, 2);
    merge8_shfl(l8, 4);
    merge8_shfl(l8, 8);
    merge8_shfl(l8, 16);
    #pragma unroll
    for (int m = 1; m < 32; m <<= 1) den += __shfl_xor_sync(0xffffffffu, den, m);

    if (lane == 0) {
        float ds = 0.0f;
        #pragma unroll
        for (int q = 0; q < KNB; q++) ds += sqrtf(fmaxf(l8[q], 0.0f));
        g_loss[row] = ds * (1.0f / KNB) + logf(den);
    }
}

// ---------------------------------------------------------------------------
__global__ void final_kernel(float* __restrict__ out, int n) {
    __shared__ float sv[256];
    const int tid = threadIdx.x;
    const float4* l4 = (const float4*)g_loss;
    float s = 0.0f;
    #pragma unroll
    for (int it = 0; it < NPTS / 1024; it++) {
        float4 v = l4[it * 256 + tid];
        s += (v.x + v.y) + (v.z + v.w);
    }
    sv[tid] = s;
    __syncthreads();
    for (int o = 128; o; o >>= 1) {
        if (tid < o) sv[tid] += sv[tid + o];
        __syncthreads();
    }
    if (tid == 0) out[0] = sv[0] / (float)n;
}

// ---------------------------------------------------------------------------
extern "C" void kernel_launch(void* const* d_in, const int* in_sizes, int n_in,
                              void* d_out, int out_size) {
    const float* x = (const float*)d_in[0];
    float* out = (float*)d_out;
    const int n = in_sizes[0] / DIM;   // 8192
    const int tri = NB * (NB + 1) / 2; // 2080

    cudaFuncSetAttribute(fused_gemm, cudaFuncAttributeMaxDynamicSharedMemorySize,
                         SMEM_TOTAL);

    pack_kernel<<<(n + 7) / 8, 256>>>(x, n);
    fused_gemm<<<tri, 256, SMEM_TOTAL>>>(n);
    merge_kernel<<<(n * 32) / 256, 256>>>(n);
    final_kernel<<<1, 256>>>(out, n);
}

// round 11
// speedup vs baseline: 6.3566x; 1.1086x over previous
#include <cuda_runtime.h>
#include <cuda_bf16.h>
#include <math.h>
#include <math_constants.h>
#include <cstdint>

#define NPTS 8192
#define DIM  128
#define KNB  8
#define NB   64            // 8192/128 blocks per side
#define SLOTS 384          // per row: 256 row-side + 128 col-side
#define COLBASE 256

// ------------------------- device scratch (no allocs) -----------------------
__device__ float g_sq[NPTS];
__device__ float g_loss[NPTS];
__device__ float g_pden[(size_t)NPTS * SLOTS];
__device__ float g_cand[(size_t)NPTS * SLOTS * KNB];
__device__ uint4 g_ph[(size_t)NPTS * 16];   // 128 bf16 (hi) per row

// ------------------------- helpers ------------------------------------------
__device__ __forceinline__ uint32_t smem_u32(const void* p) {
    uint32_t a;
    asm("{ .reg .u64 t; cvta.to.shared.u64 t, %1; cvt.u32.u64 %0, t; }"
        : "=r"(a) : "l"(p));
    return a;
}
#define SWZ(o) ((o) ^ (((o) >> 3) & 0x70))

#define CP_ASYNC16(dst, src) \
    asm volatile("cp.async.cg.shared.global [%0], [%1], 16;" \
                 :: "r"(dst), "l"(src) : "memory")
#define CP_COMMIT() asm volatile("cp.async.commit_group;" ::: "memory")
#define CP_WAIT(N)  asm volatile("cp.async.wait_group %0;" :: "n"(N) : "memory")

#define LDSM_X4(r0, r1, r2, r3, a) \
    asm volatile("ldmatrix.sync.aligned.m8n8.x4.shared.b16 {%0,%1,%2,%3}, [%4];" \
                 : "=r"(r0), "=r"(r1), "=r"(r2), "=r"(r3) : "r"(a))

#define MMA_BF16(c, a, b) \
    asm volatile("mma.sync.aligned.m16n8k16.row.col.f32.bf16.bf16.f32 " \
                 "{%0,%1,%2,%3}, {%4,%5,%6,%7}, {%8,%9}, {%0,%1,%2,%3};" \
                 : "+f"((c)[0]), "+f"((c)[1]), "+f"((c)[2]), "+f"((c)[3]) \
                 : "r"((a)[0]), "r"((a)[1]), "r"((a)[2]), "r"((a)[3]), \
                   "r"((b)[0]), "r"((b)[1]))

// SMEM: A tile 32KB at 0, B tile 32KB at 32KB (aliased to A on diagonal).
// 2 CTAs/SM -> 128KB of 227KB.
#define OFF_B    32768
#define SMEM_TOTAL 65536

// ---- MUFU transcendentals ---------------------------------------------------
__device__ __forceinline__ float rsqrt_ap(float x) {
    float y; asm("rsqrt.approx.f32 %0, %1;" : "=f"(y) : "f"(x)); return y;
}
__device__ __forceinline__ float ex2_ap(float x) {
    float y; asm("ex2.approx.f32 %0, %1;" : "=f"(y) : "f"(x)); return y;
}

// ---- sorting networks -------------------------------------------------------
__device__ __forceinline__ void cas(float& a, float& b) {
    float lo = fminf(a, b), hi = fmaxf(a, b); a = lo; b = hi;
}
__device__ __forceinline__ void sort8(float* v) {
    cas(v[0],v[1]); cas(v[2],v[3]); cas(v[4],v[5]); cas(v[6],v[7]);
    cas(v[0],v[2]); cas(v[1],v[3]); cas(v[4],v[6]); cas(v[5],v[7]);
    cas(v[1],v[2]); cas(v[5],v[6]);
    cas(v[0],v[4]); cas(v[1],v[5]); cas(v[2],v[6]); cas(v[3],v[7]);
    cas(v[2],v[4]); cas(v[3],v[5]);
    cas(v[1],v[2]); cas(v[3],v[4]); cas(v[5],v[6]);
}
__device__ __forceinline__ void bitonic8(float* v) {
    cas(v[0],v[4]); cas(v[1],v[5]); cas(v[2],v[6]); cas(v[3],v[7]);
    cas(v[0],v[2]); cas(v[1],v[3]); cas(v[4],v[6]); cas(v[5],v[7]);
    cas(v[0],v[1]); cas(v[2],v[3]); cas(v[4],v[5]); cas(v[6],v[7]);
}
__device__ __forceinline__ void merge8(float* t, const float* o) {
    float m[8];
    #pragma unroll
    for (int q = 0; q < 8; q++) m[q] = fminf(t[q], o[7 - q]);
    bitonic8(m);
    #pragma unroll
    for (int q = 0; q < 8; q++) t[q] = m[q];
}
__device__ __forceinline__ void merge8_shfl(float* t, int mask) {
    float o[8];
    #pragma unroll
    for (int q = 0; q < 8; q++) o[q] = __shfl_xor_sync(0xffffffffu, t[7 - q], mask);
    #pragma unroll
    for (int q = 0; q < 8; q++) t[q] = fminf(t[q], o[q]);
    bitonic8(t);
}

// ---------------------------------------------------------------------------
// fused pack (hi only) + sqnorm: one warp per row
// ---------------------------------------------------------------------------
__global__ void pack_kernel(const float* __restrict__ x, int n) {
    int warp = (blockIdx.x * blockDim.x + threadIdx.x) >> 5;
    int lane = threadIdx.x & 31;
    if (warp >= n) return;
    float4 v = ((const float4*)(x + (size_t)warp * DIM))[lane];

    float s = v.x * v.x + v.y * v.y + v.z * v.z + v.w * v.w;
    #pragma unroll
    for (int o = 16; o; o >>= 1) s += __shfl_xor_sync(0xffffffffu, s, o);
    if (lane == 0) g_sq[warp] = s;

    __nv_bfloat162* ph2 = (__nv_bfloat162*)g_ph;   // 64 pairs per row
    size_t rb = (size_t)warp * 64;
    ph2[rb + lane * 2]     = __nv_bfloat162(__float2bfloat16(v.x), __float2bfloat16(v.y));
    ph2[rb + lane * 2 + 1] = __nv_bfloat162(__float2bfloat16(v.z), __float2bfloat16(v.w));
}

// ---------------------------------------------------------------------------
// Symmetric fused GEMM: 128x128 tiles over upper triangle, warps 2(m)x4(n)
// of 64x32. K=128 hi-only bf16; both tiles SMEM-resident, zero mainloop syncs.
// 2 CTAs/SM.
// ---------------------------------------------------------------------------
__global__ __launch_bounds__(256, 2) void fused_gemm(int n) {
    extern __shared__ __align__(16) char smem[];
    const uint32_t sb = smem_u32(smem);
    const int tid = threadIdx.x;
    const int wid = tid >> 5;
    const int lane = tid & 31;
    const int wm = wid & 1;          // 64-row half
    const int wn = wid >> 1;         // 32-col strip
    const int mr = wm * 64;
    const int nr = wn * 32;

    int rem = blockIdx.x, bi = 0;
    while (rem >= NB - bi) { rem -= NB - bi; bi++; }
    const int bj = bi + rem;
    const int i0 = bi * 128, j0 = bj * 128;
    const bool diag = (bi == bj);

    // prologue: A tile (2 chunks of 64k as 128 rows x 128B swizzled each);
    // B tile likewise unless diagonal (B aliases A).
    #pragma unroll
    for (int r = 0; r < 8; r++) {
        int idx = tid + r * 256;                  // 0..2047
        int kc = idx >> 10, w = idx & 1023;
        int row = w >> 3, q = w & 7;
        const uint4* src = &g_ph[(size_t)(i0 + row) * 16 + kc * 8 + q];
        CP_ASYNC16(sb + kc * 16384 + SWZ(row * 128 + q * 16), src);
    }
    if (!diag) {
        #pragma unroll
        for (int r = 0; r < 8; r++) {
            int idx = tid + r * 256;
            int kc = idx >> 10, w = idx & 1023;
            int row = w >> 3, q = w & 7;
            const uint4* src = &g_ph[(size_t)(j0 + row) * 16 + kc * 8 + q];
            CP_ASYNC16(sb + OFF_B + kc * 16384 + SWZ(row * 128 + q * 16), src);
        }
    }
    CP_COMMIT();
    CP_WAIT(0);
    __syncthreads();

    const uint32_t bbase = diag ? sb : (sb + OFF_B);
    const int row_off = lane & 15;
    const int colh2 = (lane >> 4) * 16;
    const uint32_t aRow = (uint32_t)(mr + row_off) * 128;
    const uint32_t bRow = (uint32_t)(nr + row_off) * 128;

    float acc[4][4][4];
    #pragma unroll
    for (int i = 0; i < 4; i++)
        #pragma unroll
        for (int j = 0; j < 4; j++)
            #pragma unroll
            for (int q = 0; q < 4; q++) acc[i][j][q] = 0.0f;

    #pragma unroll
    for (int c = 0; c < 2; c++) {
        uint32_t sA = sb + c * 16384;
        uint32_t sB = bbase + c * 16384;
        #pragma unroll
        for (int ks = 0; ks < 4; ks++) {
            uint32_t colb = ks * 32 + colh2;
            uint32_t aF[4][4], bF[4][2];
            #pragma unroll
            for (int i = 0; i < 4; i++) {
                uint32_t ad = sA + SWZ(aRow + i * 2048 + colb);
                LDSM_X4(aF[i][0], aF[i][1], aF[i][2], aF[i][3], ad);
            }
            #pragma unroll
            for (int jj = 0; jj < 2; jj++) {
                uint32_t r0, r1, r2, r3;
                uint32_t bd = sB + SWZ(bRow + jj * 2048 + colb);
                LDSM_X4(r0, r1, r2, r3, bd);
                bF[2 * jj][0] = r0; bF[2 * jj][1] = r2;
                bF[2 * jj + 1][0] = r1; bF[2 * jj + 1][1] = r3;
            }
            #pragma unroll
            for (int i = 0; i < 4; i++)
                #pragma unroll
                for (int j = 0; j < 4; j++)
                    MMA_BF16(acc[i][j], aF[i], bF[j]);
        }
    }

    // ---------------- fused epilogue ----------------
    const int g = lane >> 2, t = lane & 3;
    const int scol = j0 + nr + t * 2;
    const float NL2E = -1.4426950408889634f;

    float sqc[8], sqr[8], colden[8];
    #pragma unroll
    for (int j = 0; j < 4; j++) {
        #pragma unroll
        for (int e = 0; e < 2; e++) {
            sqc[j * 2 + e] = g_sq[scol + j * 8 + e];
            colden[j * 2 + e] = 0.0f;
        }
    }
    #pragma unroll
    for (int i = 0; i < 4; i++)
        #pragma unroll
        for (int h = 0; h < 2; h++)
            sqr[i * 2 + h] = g_sq[i0 + mr + i * 16 + h * 8 + g];

    const int rslot = (bj - bi) * 4 + wn;
    #pragma unroll
    for (int i = 0; i < 4; i++) {
        #pragma unroll
        for (int h = 0; h < 2; h++) {
            const int rg = i0 + mr + i * 16 + h * 8 + g;
            const float sqi = sqr[i * 2 + h];
            float v8[8];
            float den = 0.0f;
            #pragma unroll
            for (int j = 0; j < 4; j++) {
                #pragma unroll
                for (int e = 0; e < 2; e++) {
                    const int je = j * 2 + e;
                    float dot = acc[i][j][h * 2 + e];
                    int cg = scol + j * 8 + e;
                    float d2 = fmaxf(fmaf(-2.0f, dot, sqi + sqc[je]), 0.0f);
                    bool self = diag && (cg == rg);
                    float ex = ex2_ap(d2 * rsqrt_ap(d2) * NL2E);
                    ex = self ? 0.0f : ex;      // kills the d2==0 NaN
                    den += ex;
                    colden[je] += ex;
                    v8[je] = self ? CUDART_INF_F : d2;
                }
            }
            den += __shfl_xor_sync(0xffffffffu, den, 1);
            den += __shfl_xor_sync(0xffffffffu, den, 2);
            sort8(v8);
            merge8_shfl(v8, 1);
            merge8_shfl(v8, 2);
            if (t == 0) {
                g_pden[(size_t)rg * SLOTS + rslot] = den;
                float4* dst = (float4*)&g_cand[((size_t)rg * SLOTS + rslot) * KNB];
                dst[0] = make_float4(v8[0], v8[1], v8[2], v8[3]);
                dst[1] = make_float4(v8[4], v8[5], v8[6], v8[7]);
            }
        }
    }

    if (!diag) {
        const int cslot = COLBASE + bi * 2 + wm;
        #pragma unroll
        for (int j = 0; j < 4; j++) {
            #pragma unroll
            for (int e = 0; e < 2; e++) {
                const int je = j * 2 + e;
                const int cg = scol + j * 8 + e;
                float c8[8];
                #pragma unroll
                for (int i = 0; i < 4; i++) {
                    #pragma unroll
                    for (int h = 0; h < 2; h++) {
                        float dot = acc[i][j][h * 2 + e];
                        float d2 = fmaxf(fmaf(-2.0f, dot, sqr[i * 2 + h] + sqc[je]), 0.0f);
                        c8[i * 2 + h] = d2;   // off-diag only -> no self here
                    }
                }
                sort8(c8);
                merge8_shfl(c8, 4);
                merge8_shfl(c8, 8);
                merge8_shfl(c8, 16);
                float cd = colden[je];
                cd += __shfl_xor_sync(0xffffffffu, cd, 4);
                cd += __shfl_xor_sync(0xffffffffu, cd, 8);
                cd += __shfl_xor_sync(0xffffffffu, cd, 16);
                if (g == 0) {
                    g_pden[(size_t)cg * SLOTS + cslot] = cd;
                    float4* dst = (float4*)&g_cand[((size_t)cg * SLOTS + cslot) * KNB];
                    dst[0] = make_float4(c8[0], c8[1], c8[2], c8[3]);
                    dst[1] = make_float4(c8[4], c8[5], c8[6], c8[7]);
                }
            }
        }
    }
}

// ---------------------------------------------------------------------------
// merge kernel: one warp per row; software-pipelined slot loads (MLP=2).
// ---------------------------------------------------------------------------
__global__ __launch_bounds__(256) void merge_kernel(int n) {
    const int row = (blockIdx.x * 256 + threadIdx.x) >> 5;
    const int lane = threadIdx.x & 31;
    if (row >= n) return;
    const int bi = row >> 7;
    const int nrow = (NB - bi) * 4;
    const int ntot = nrow + 2 * bi;

    float l8[8];
    #pragma unroll
    for (int q = 0; q < 8; q++) l8[q] = CUDART_INF_F;
    float den = 0.0f;

    int s = lane;
    float4 a, b; float pd = 0.0f;
    if (s < ntot) {
        int slot = (s < nrow) ? s : (COLBASE + (s - nrow));
        const float4* src = (const float4*)&g_cand[((size_t)row * SLOTS + slot) * KNB];
        a = src[0]; b = src[1];
        pd = g_pden[(size_t)row * SLOTS + slot];
    }
    while (s < ntot) {
        int s2 = s + 32;
        float4 a2, b2; float pd2 = 0.0f;
        if (s2 < ntot) {
            int slot2 = (s2 < nrow) ? s2 : (COLBASE + (s2 - nrow));
            const float4* src2 = (const float4*)&g_cand[((size_t)row * SLOTS + slot2) * KNB];
            a2 = src2[0]; b2 = src2[1];
            pd2 = g_pden[(size_t)row * SLOTS + slot2];
        }
        float o[8];
        o[0] = a.x; o[1] = a.y; o[2] = a.z; o[3] = a.w;
        o[4] = b.x; o[5] = b.y; o[6] = b.z; o[7] = b.w;
        merge8(l8, o);
        den += pd;
        a = a2; b = b2; pd = pd2; s = s2;
    }
    merge8_shfl(l8, 1);
    merge8_shfl(l8, 2);
    merge8_shfl(l8, 4);
    merge8_shfl(l8, 8);
    merge8_shfl(l8, 16);
    #pragma unroll
    for (int m = 1; m < 32; m <<= 1) den += __shfl_xor_sync(0xffffffffu, den, m);

    if (lane == 0) {
        float ds = 0.0f;
        #pragma unroll
        for (int q = 0; q < KNB; q++) ds += sqrtf(fmaxf(l8[q], 0.0f));
        g_loss[row] = ds * (1.0f / KNB) + logf(den);
    }
}

// ---------------------------------------------------------------------------
__global__ void final_kernel(float* __restrict__ out, int n) {
    __shared__ float sv[256];
    const int tid = threadIdx.x;
    const float4* l4 = (const float4*)g_loss;
    float s = 0.0f;
    #pragma unroll
    for (int it = 0; it < NPTS / 1024; it++) {
        float4 v = l4[it * 256 + tid];
        s += (v.x + v.y) + (v.z + v.w);
    }
    sv[tid] = s;
    __syncthreads();
    for (int o = 128; o; o >>= 1) {
        if (tid < o) sv[tid] += sv[tid + o];
        __syncthreads();
    }
    if (tid == 0) out[0] = sv[0] / (float)n;
}

// ---------------------------------------------------------------------------
extern "C" void kernel_launch(void* const* d_in, const int* in_sizes, int n_in,
                              void* d_out, int out_size) {
    const float* x = (const float*)d_in[0];
    float* out = (float*)d_out;
    const int n = in_sizes[0] / DIM;   // 8192
    const int tri = NB * (NB + 1) / 2; // 2080

    cudaFuncSetAttribute(fused_gemm, cudaFuncAttributeMaxDynamicSharedMemorySize,
                         SMEM_TOTAL);

    pack_kernel<<<(n + 7) / 8, 256>>>(x, n);
    fused_gemm<<<tri, 256, SMEM_TOTAL>>>(n);
    merge_kernel<<<(n * 32) / 256, 256>>>(n);
    final_kernel<<<1, 256>>>(out, n);
}

// round 12
// speedup vs baseline: 7.4526x; 1.1724x over previous
#include <cuda_runtime.h>
#include <cuda_bf16.h>
#include <math.h>
#include <math_constants.h>
#include <cstdint>

#define NPTS 8192
#define DIM  128
#define KNB  8
#define NB   64            // 8192/128 blocks per side
#define SLOTS 384          // per row: 256 row-side + 128 col-side
#define COLBASE 256

// ------------------------- device scratch (no allocs) -----------------------
__device__ float g_sq[NPTS];
__device__ float g_loss[NPTS];
__device__ float g_pden[(size_t)NPTS * SLOTS];
__device__ float g_cand[(size_t)NPTS * SLOTS * KNB];
__device__ uint4 g_ph[(size_t)NPTS * 16];   // 128 bf16 (hi) per row

// ------------------------- helpers ------------------------------------------
__device__ __forceinline__ uint32_t smem_u32(const void* p) {
    uint32_t a;
    asm("{ .reg .u64 t; cvta.to.shared.u64 t, %1; cvt.u32.u64 %0, t; }"
        : "=r"(a) : "l"(p));
    return a;
}
#define SWZ(o) ((o) ^ (((o) >> 3) & 0x70))

#define CP_ASYNC16(dst, src) \
    asm volatile("cp.async.cg.shared.global [%0], [%1], 16;" \
                 :: "r"(dst), "l"(src) : "memory")
#define CP_COMMIT() asm volatile("cp.async.commit_group;" ::: "memory")
#define CP_WAIT(N)  asm volatile("cp.async.wait_group %0;" :: "n"(N) : "memory")

#define LDSM_X4(r0, r1, r2, r3, a) \
    asm volatile("ldmatrix.sync.aligned.m8n8.x4.shared.b16 {%0,%1,%2,%3}, [%4];" \
                 : "=r"(r0), "=r"(r1), "=r"(r2), "=r"(r3) : "r"(a))

#define MMA_BF16(c, a, b) \
    asm volatile("mma.sync.aligned.m16n8k16.row.col.f32.bf16.bf16.f32 " \
                 "{%0,%1,%2,%3}, {%4,%5,%6,%7}, {%8,%9}, {%0,%1,%2,%3};" \
                 : "+f"((c)[0]), "+f"((c)[1]), "+f"((c)[2]), "+f"((c)[3]) \
                 : "r"((a)[0]), "r"((a)[1]), "r"((a)[2]), "r"((a)[3]), \
                   "r"((b)[0]), "r"((b)[1]))

// SMEM: A tile 32KB at 0, B tile 32KB at 32KB (aliased to A on diagonal).
// 2 CTAs/SM -> 128KB of 227KB.
#define OFF_B    32768
#define SMEM_TOTAL 65536

// ---- MUFU transcendentals ---------------------------------------------------
__device__ __forceinline__ float rsqrt_ap(float x) {
    float y; asm("rsqrt.approx.f32 %0, %1;" : "=f"(y) : "f"(x)); return y;
}
__device__ __forceinline__ float ex2_ap(float x) {
    float y; asm("ex2.approx.f32 %0, %1;" : "=f"(y) : "f"(x)); return y;
}

// ---- sorting networks -------------------------------------------------------
__device__ __forceinline__ void cas(float& a, float& b) {
    float lo = fminf(a, b), hi = fmaxf(a, b); a = lo; b = hi;
}
__device__ __forceinline__ void sort8(float* v) {
    cas(v[0],v[1]); cas(v[2],v[3]); cas(v[4],v[5]); cas(v[6],v[7]);
    cas(v[0],v[2]); cas(v[1],v[3]); cas(v[4],v[6]); cas(v[5],v[7]);
    cas(v[1],v[2]); cas(v[5],v[6]);
    cas(v[0],v[4]); cas(v[1],v[5]); cas(v[2],v[6]); cas(v[3],v[7]);
    cas(v[2],v[4]); cas(v[3],v[5]);
    cas(v[1],v[2]); cas(v[3],v[4]); cas(v[5],v[6]);
}
__device__ __forceinline__ void bitonic8(float* v) {
    cas(v[0],v[4]); cas(v[1],v[5]); cas(v[2],v[6]); cas(v[3],v[7]);
    cas(v[0],v[2]); cas(v[1],v[3]); cas(v[4],v[6]); cas(v[5],v[7]);
    cas(v[0],v[1]); cas(v[2],v[3]); cas(v[4],v[5]); cas(v[6],v[7]);
}
__device__ __forceinline__ void merge8(float* t, const float* o) {
    float m[8];
    #pragma unroll
    for (int q = 0; q < 8; q++) m[q] = fminf(t[q], o[7 - q]);
    bitonic8(m);
    #pragma unroll
    for (int q = 0; q < 8; q++) t[q] = m[q];
}
__device__ __forceinline__ void merge8_shfl(float* t, int mask) {
    float o[8];
    #pragma unroll
    for (int q = 0; q < 8; q++) o[q] = __shfl_xor_sync(0xffffffffu, t[7 - q], mask);
    #pragma unroll
    for (int q = 0; q < 8; q++) t[q] = fminf(t[q], o[q]);
    bitonic8(t);
}
// level-1 work-split merge: lane owns list `mine`; partner (xor mask) owns the
// other. Sends the non-owned list reversed, merges received into owned.
__device__ __forceinline__ void merge8_pair(float* r, const float* va,
                                            const float* vb, bool ownb,
                                            int mask) {
    #pragma unroll
    for (int q = 0; q < 8; q++) {
        float sendv = ownb ? va[7 - q] : vb[7 - q];
        float recvv = __shfl_xor_sync(0xffffffffu, sendv, mask);
        float minev = ownb ? vb[q] : va[q];
        r[q] = fminf(minev, recvv);
    }
    bitonic8(r);
}

// ---------------------------------------------------------------------------
// fused pack (hi only) + sqnorm: one warp per row
// ---------------------------------------------------------------------------
__global__ void pack_kernel(const float* __restrict__ x, int n) {
    int warp = (blockIdx.x * blockDim.x + threadIdx.x) >> 5;
    int lane = threadIdx.x & 31;
    if (warp >= n) return;
    float4 v = ((const float4*)(x + (size_t)warp * DIM))[lane];

    float s = v.x * v.x + v.y * v.y + v.z * v.z + v.w * v.w;
    #pragma unroll
    for (int o = 16; o; o >>= 1) s += __shfl_xor_sync(0xffffffffu, s, o);
    if (lane == 0) g_sq[warp] = s;

    __nv_bfloat162* ph2 = (__nv_bfloat162*)g_ph;   // 64 pairs per row
    size_t rb = (size_t)warp * 64;
    ph2[rb + lane * 2]     = __nv_bfloat162(__float2bfloat16(v.x), __float2bfloat16(v.y));
    ph2[rb + lane * 2 + 1] = __nv_bfloat162(__float2bfloat16(v.z), __float2bfloat16(v.w));
}

// ---------------------------------------------------------------------------
// Symmetric fused GEMM: 128x128 tiles over upper triangle, warps 2(m)x4(n)
// of 64x32. K=128 hi-only bf16; tiles SMEM-resident. Work-split merges.
// 2 CTAs/SM.
// ---------------------------------------------------------------------------
__global__ __launch_bounds__(256, 2) void fused_gemm(int n) {
    extern __shared__ __align__(16) char smem[];
    const uint32_t sb = smem_u32(smem);
    const int tid = threadIdx.x;
    const int wid = tid >> 5;
    const int lane = tid & 31;
    const int wm = wid & 1;          // 64-row half
    const int wn = wid >> 1;         // 32-col strip
    const int mr = wm * 64;
    const int nr = wn * 32;

    int rem = blockIdx.x, bi = 0;
    while (rem >= NB - bi) { rem -= NB - bi; bi++; }
    const int bj = bi + rem;
    const int i0 = bi * 128, j0 = bj * 128;
    const bool diag = (bi == bj);

    // prologue: A tile; B tile unless diagonal (B aliases A).
    #pragma unroll
    for (int r = 0; r < 8; r++) {
        int idx = tid + r * 256;                  // 0..2047
        int kc = idx >> 10, w = idx & 1023;
        int row = w >> 3, q = w & 7;
        const uint4* src = &g_ph[(size_t)(i0 + row) * 16 + kc * 8 + q];
        CP_ASYNC16(sb + kc * 16384 + SWZ(row * 128 + q * 16), src);
    }
    if (!diag) {
        #pragma unroll
        for (int r = 0; r < 8; r++) {
            int idx = tid + r * 256;
            int kc = idx >> 10, w = idx & 1023;
            int row = w >> 3, q = w & 7;
            const uint4* src = &g_ph[(size_t)(j0 + row) * 16 + kc * 8 + q];
            CP_ASYNC16(sb + OFF_B + kc * 16384 + SWZ(row * 128 + q * 16), src);
        }
    }
    CP_COMMIT();
    CP_WAIT(0);
    __syncthreads();

    const uint32_t bbase = diag ? sb : (sb + OFF_B);
    const int row_off = lane & 15;
    const int colh2 = (lane >> 4) * 16;
    const uint32_t aRow = (uint32_t)(mr + row_off) * 128;
    const uint32_t bRow = (uint32_t)(nr + row_off) * 128;

    float acc[4][4][4];
    #pragma unroll
    for (int i = 0; i < 4; i++)
        #pragma unroll
        for (int j = 0; j < 4; j++)
            #pragma unroll
            for (int q = 0; q < 4; q++) acc[i][j][q] = 0.0f;

    #pragma unroll
    for (int c = 0; c < 2; c++) {
        uint32_t sA = sb + c * 16384;
        uint32_t sB = bbase + c * 16384;
        #pragma unroll
        for (int ks = 0; ks < 4; ks++) {
            uint32_t colb = ks * 32 + colh2;
            uint32_t aF[4][4], bF[4][2];
            #pragma unroll
            for (int i = 0; i < 4; i++) {
                uint32_t ad = sA + SWZ(aRow + i * 2048 + colb);
                LDSM_X4(aF[i][0], aF[i][1], aF[i][2], aF[i][3], ad);
            }
            #pragma unroll
            for (int jj = 0; jj < 2; jj++) {
                uint32_t r0, r1, r2, r3;
                uint32_t bd = sB + SWZ(bRow + jj * 2048 + colb);
                LDSM_X4(r0, r1, r2, r3, bd);
                bF[2 * jj][0] = r0; bF[2 * jj][1] = r2;
                bF[2 * jj + 1][0] = r1; bF[2 * jj + 1][1] = r3;
            }
            #pragma unroll
            for (int i = 0; i < 4; i++)
                #pragma unroll
                for (int j = 0; j < 4; j++)
                    MMA_BF16(acc[i][j], aF[i], bF[j]);
        }
    }

    // ---------------- fused epilogue (work-split merges) ----------------
    const int g = lane >> 2, t = lane & 3;
    const int scol = j0 + nr + t * 2;
    const float NL2E = -1.4426950408889634f;

    float sqc[8], sqr[8], colden[8];
    #pragma unroll
    for (int j = 0; j < 4; j++) {
        #pragma unroll
        for (int e = 0; e < 2; e++) {
            sqc[j * 2 + e] = g_sq[scol + j * 8 + e];
            colden[j * 2 + e] = 0.0f;
        }
    }
    #pragma unroll
    for (int i = 0; i < 4; i++)
        #pragma unroll
        for (int h = 0; h < 2; h++)
            sqr[i * 2 + h] = g_sq[i0 + mr + i * 16 + h * 8 + g];

    const int rslot = (bj - bi) * 4 + wn;
    const bool own_h1 = (lane & 1);          // t parity: odd t owns h=1
    #pragma unroll
    for (int i = 0; i < 4; i++) {
        const int rga = i0 + mr + i * 16 + g;       // h = 0
        const int rgb = rga + 8;                    // h = 1
        const float sqia = sqr[i * 2], sqib = sqr[i * 2 + 1];
        float v8a[8], v8b[8];
        float den_a = 0.0f, den_b = 0.0f;
        #pragma unroll
        for (int j = 0; j < 4; j++) {
            #pragma unroll
            for (int e = 0; e < 2; e++) {
                const int je = j * 2 + e;
                const int cg = scol + j * 8 + e;
                float d2a = fmaxf(fmaf(-2.0f, acc[i][j][e], sqia + sqc[je]), 0.0f);
                bool sa = diag && (cg == rga);
                float exa = ex2_ap(d2a * rsqrt_ap(d2a) * NL2E);
                exa = sa ? 0.0f : exa;
                den_a += exa; colden[je] += exa;
                v8a[je] = sa ? CUDART_INF_F : d2a;

                float d2b = fmaxf(fmaf(-2.0f, acc[i][j][2 + e], sqib + sqc[je]), 0.0f);
                bool sbx = diag && (cg == rgb);
                float exb = ex2_ap(d2b * rsqrt_ap(d2b) * NL2E);
                exb = sbx ? 0.0f : exb;
                den_b += exb; colden[je] += exb;
                v8b[je] = sbx ? CUDART_INF_F : d2b;
            }
        }
        den_a += __shfl_xor_sync(0xffffffffu, den_a, 1);
        den_a += __shfl_xor_sync(0xffffffffu, den_a, 2);
        den_b += __shfl_xor_sync(0xffffffffu, den_b, 1);
        den_b += __shfl_xor_sync(0xffffffffu, den_b, 2);
        sort8(v8a); sort8(v8b);
        float r8[8];
        merge8_pair(r8, v8a, v8b, own_h1, 1);   // t0<->t1, t2<->t3
        merge8_shfl(r8, 2);                     // complete over 4 t-lanes
        if (t < 2) {                            // t==0 stores h=0, t==1 h=1
            const int rg_own = own_h1 ? rgb : rga;
            g_pden[(size_t)rg_own * SLOTS + rslot] = own_h1 ? den_b : den_a;
            float4* dst = (float4*)&g_cand[((size_t)rg_own * SLOTS + rslot) * KNB];
            dst[0] = make_float4(r8[0], r8[1], r8[2], r8[3]);
            dst[1] = make_float4(r8[4], r8[5], r8[6], r8[7]);
        }
    }

    if (!diag) {
        const int cslot = COLBASE + bi * 2 + wm;
        const bool own_e1 = (lane >> 2) & 1;    // g parity: odd g owns e=1
        #pragma unroll
        for (int j = 0; j < 4; j++) {
            float c8a[8], c8b[8];
            #pragma unroll
            for (int i = 0; i < 4; i++) {
                #pragma unroll
                for (int h = 0; h < 2; h++) {
                    float sq_ih = sqr[i * 2 + h];
                    c8a[i * 2 + h] = fmaxf(fmaf(-2.0f, acc[i][j][h * 2],     sq_ih + sqc[j * 2]),     0.0f);
                    c8b[i * 2 + h] = fmaxf(fmaf(-2.0f, acc[i][j][h * 2 + 1], sq_ih + sqc[j * 2 + 1]), 0.0f);
                }
            }
            sort8(c8a); sort8(c8b);
            float r8[8];
            merge8_pair(r8, c8a, c8b, own_e1, 4);   // g pairs
            merge8_shfl(r8, 8);
            merge8_shfl(r8, 16);                    // complete over 8 g-lanes
            float cda = colden[j * 2], cdb = colden[j * 2 + 1];
            cda += __shfl_xor_sync(0xffffffffu, cda, 4);
            cda += __shfl_xor_sync(0xffffffffu, cda, 8);
            cda += __shfl_xor_sync(0xffffffffu, cda, 16);
            cdb += __shfl_xor_sync(0xffffffffu, cdb, 4);
            cdb += __shfl_xor_sync(0xffffffffu, cdb, 8);
            cdb += __shfl_xor_sync(0xffffffffu, cdb, 16);
            if (g < 2) {                            // g==0 stores e=0, g==1 e=1
                const int cg = scol + j * 8 + (own_e1 ? 1 : 0);
                g_pden[(size_t)cg * SLOTS + cslot] = own_e1 ? cdb : cda;
                float4* dst = (float4*)&g_cand[((size_t)cg * SLOTS + cslot) * KNB];
                dst[0] = make_float4(r8[0], r8[1], r8[2], r8[3]);
                dst[1] = make_float4(r8[4], r8[5], r8[6], r8[7]);
            }
        }
    }
}

// ---------------------------------------------------------------------------
// merge kernel: one warp per row; software-pipelined slot loads (MLP=2).
// ---------------------------------------------------------------------------
__global__ __launch_bounds__(256) void merge_kernel(int n) {
    const int row = (blockIdx.x * 256 + threadIdx.x) >> 5;
    const int lane = threadIdx.x & 31;
    if (row >= n) return;
    const int bi = row >> 7;
    const int nrow = (NB - bi) * 4;
    const int ntot = nrow + 2 * bi;

    float l8[8];
    #pragma unroll
    for (int q = 0; q < 8; q++) l8[q] = CUDART_INF_F;
    float den = 0.0f;

    int s = lane;
    float4 a, b; float pd = 0.0f;
    if (s < ntot) {
        int slot = (s < nrow) ? s : (COLBASE + (s - nrow));
        const float4* src = (const float4*)&g_cand[((size_t)row * SLOTS + slot) * KNB];
        a = src[0]; b = src[1];
        pd = g_pden[(size_t)row * SLOTS + slot];
    }
    while (s < ntot) {
        int s2 = s + 32;
        float4 a2, b2; float pd2 = 0.0f;
        if (s2 < ntot) {
            int slot2 = (s2 < nrow) ? s2 : (COLBASE + (s2 - nrow));
            const float4* src2 = (const float4*)&g_cand[((size_t)row * SLOTS + slot2) * KNB];
            a2 = src2[0]; b2 = src2[1];
            pd2 = g_pden[(size_t)row * SLOTS + slot2];
        }
        float o[8];
        o[0] = a.x; o[1] = a.y; o[2] = a.z; o[3] = a.w;
        o[4] = b.x; o[5] = b.y; o[6] = b.z; o[7] = b.w;
        merge8(l8, o);
        den += pd;
        a = a2; b = b2; pd = pd2; s = s2;
    }
    merge8_shfl(l8, 1);
    merge8_shfl(l8, 2);
    merge8_shfl(l8, 4);
    merge8_shfl(l8, 8);
    merge8_shfl(l8, 16);
    #pragma unroll
    for (int m = 1; m < 32; m <<= 1) den += __shfl_xor_sync(0xffffffffu, den, m);

    if (lane == 0) {
        float ds = 0.0f;
        #pragma unroll
        for (int q = 0; q < KNB; q++) ds += sqrtf(fmaxf(l8[q], 0.0f));
        g_loss[row] = ds * (1.0f / KNB) + logf(den);
    }
}

// ---------------------------------------------------------------------------
__global__ void final_kernel(float* __restrict__ out, int n) {
    __shared__ float sv[256];
    const int tid = threadIdx.x;
    const float4* l4 = (const float4*)g_loss;
    float s = 0.0f;
    #pragma unroll
    for (int it = 0; it < NPTS / 1024; it++) {
        float4 v = l4[it * 256 + tid];
        s += (v.x + v.y) + (v.z + v.w);
    }
    sv[tid] = s;
    __syncthreads();
    for (int o = 128; o; o >>= 1) {
        if (tid < o) sv[tid] += sv[tid + o];
        __syncthreads();
    }
    if (tid == 0) out[0] = sv[0] / (float)n;
}

// ---------------------------------------------------------------------------
extern "C" void kernel_launch(void* const* d_in, const int* in_sizes, int n_in,
                              void* d_out, int out_size) {
    const float* x = (const float*)d_in[0];
    float* out = (float*)d_out;
    const int n = in_sizes[0] / DIM;   // 8192
    const int tri = NB * (NB + 1) / 2; // 2080

    cudaFuncSetAttribute(fused_gemm, cudaFuncAttributeMaxDynamicSharedMemorySize,
                         SMEM_TOTAL);

    pack_kernel<<<(n + 7) / 8, 256>>>(x, n);
    fused_gemm<<<tri, 256, SMEM_TOTAL>>>(n);
    merge_kernel<<<(n * 32) / 256, 256>>>(n);
    final_kernel<<<1, 256>>>(out, n);
}